// round 1
// baseline (speedup 1.0000x reference)
#include <cuda_runtime.h>
#include <math.h>

// TriangleMultiplication: B=2, N=256, D=256 (N==D)
//   a = pair@Wa+ba; b = pair@Wb+bb; g = sigmoid(pair@Wg+bg)
//   ab[b,i] = a[b,i] @ b[b,i]  (per-slice 256x256x256 GEMM, 512 slices)
//   out = (g*ab)@Wo + bo
//
// Round 1: fp32 baseline. Three tiled GEMM kernels (128x128 CTA tile, 8x8
// per-thread micro-tile) using packed fma.rn.f32x2 (FFMA2) for 2x FFMA
// throughput. Scratch intermediates live in __device__ globals (no allocs;
// graph-capturable: plain launches on the default stream only).

#define BM 128
#define BN 128
#define BK 8
#define NELEM 33554432  // 2*256*256*256

static __device__ float g_A[NELEM];   // a projection
static __device__ float g_Bp[NELEM];  // b projection
static __device__ float g_G[NELEM];   // sigmoid(g) projection
static __device__ float g_H[NELEM];   // g * (a@b)

typedef unsigned long long ull;

__device__ __forceinline__ ull pack2(float x, float y) {
    ull r; asm("mov.b64 %0, {%1, %2};" : "=l"(r) : "f"(x), "f"(y)); return r;
}
__device__ __forceinline__ void unpack2(ull v, float &x, float &y) {
    asm("mov.b64 {%0, %1}, %2;" : "=f"(x), "=f"(y) : "l"(v));
}
__device__ __forceinline__ void fma2(ull &d, ull a, ull b) {
    asm("fma.rn.f32x2 %0, %1, %2, %0;" : "+l"(d) : "l"(a), "l"(b));
}

// C tile (m0..m0+127, n0..n0+127) of A[M,K] @ B[K,N], both row-major.
// 256 threads; each thread accumulates an 8x8 micro-tile stored as 8x4
// packed f32x2 pairs (pairs are adjacent columns).
__device__ __forceinline__ void gemm128(const float* __restrict__ A, int lda,
                                        const float* __restrict__ B, int ldb,
                                        int m0, int n0, int K,
                                        ull acc[8][4])
{
    __shared__ float As[BK][BM];  // transposed: As[k][m]
    __shared__ float Bs[BK][BN];  // Bs[k][n]

    const int tid = threadIdx.x;
    const int tx = tid & 15, ty = tid >> 4;
    const int ar = tid >> 1,  ac = (tid & 1) * 4;   // A tile: 128 rows x 8 k
    const int br = tid >> 5,  bc = (tid & 31) * 4;  // B tile: 8 k x 128 cols

    const ull z = pack2(0.f, 0.f);
#pragma unroll
    for (int i = 0; i < 8; i++)
#pragma unroll
        for (int j = 0; j < 4; j++) acc[i][j] = z;

    for (int k0 = 0; k0 < K; k0 += BK) {
        float4 av = *(const float4*)&A[(size_t)(m0 + ar) * lda + k0 + ac];
        float4 bv = *(const float4*)&B[(size_t)(k0 + br) * ldb + n0 + bc];
        __syncthreads();  // protect previous iteration's smem reads
        As[ac + 0][ar] = av.x;
        As[ac + 1][ar] = av.y;
        As[ac + 2][ar] = av.z;
        As[ac + 3][ar] = av.w;
        *(float4*)&Bs[br][bc] = bv;
        __syncthreads();
#pragma unroll
        for (int kk = 0; kk < BK; ++kk) {
            float4 a0 = *(const float4*)&As[kk][ty * 4];
            float4 a1 = *(const float4*)&As[kk][64 + ty * 4];
            ull b0 = *(const ull*)&Bs[kk][tx * 4];
            ull b1 = *(const ull*)&Bs[kk][tx * 4 + 2];
            ull b2 = *(const ull*)&Bs[kk][64 + tx * 4];
            ull b3 = *(const ull*)&Bs[kk][64 + tx * 4 + 2];
            ull ap[8];
            ap[0] = pack2(a0.x, a0.x); ap[1] = pack2(a0.y, a0.y);
            ap[2] = pack2(a0.z, a0.z); ap[3] = pack2(a0.w, a0.w);
            ap[4] = pack2(a1.x, a1.x); ap[5] = pack2(a1.y, a1.y);
            ap[6] = pack2(a1.z, a1.z); ap[7] = pack2(a1.w, a1.w);
#pragma unroll
            for (int i = 0; i < 8; i++) {
                fma2(acc[i][0], ap[i], b0);
                fma2(acc[i][1], ap[i], b1);
                fma2(acc[i][2], ap[i], b2);
                fma2(acc[i][3], ap[i], b3);
            }
        }
    }
    __syncthreads();
}

__device__ __forceinline__ int row_of(int i, int ty) {
    return (i < 4) ? (ty * 4 + i) : (64 + ty * 4 + (i - 4));
}
__device__ __forceinline__ int col_of(int jp, int tx) {
    return (jp < 2) ? (tx * 4 + 2 * jp) : (64 + tx * 4 + 2 * (jp - 2));
}

// Kernel 1: all three input projections. grid (6, 1024):
//   x = w*2 + ntile  (w in {0=a,1=b,2=g}), y = m-tile over 131072 rows.
extern "C" __global__ void __launch_bounds__(256)
proj_kernel(const float* __restrict__ pair,
            const float* __restrict__ Wa, const float* __restrict__ ba,
            const float* __restrict__ Wb, const float* __restrict__ bb,
            const float* __restrict__ Wg, const float* __restrict__ bg)
{
    const int w = blockIdx.x >> 1, nt = blockIdx.x & 1;
    const float* W    = (w == 0) ? Wa : ((w == 1) ? Wb : Wg);
    const float* bias = (w == 0) ? ba : ((w == 1) ? bb : bg);
    float* out        = (w == 0) ? g_A : ((w == 1) ? g_Bp : g_G);
    const int m0 = blockIdx.y * BM, n0 = nt * BN;

    ull acc[8][4];
    gemm128(pair, 256, W, 256, m0, n0, 256, acc);

    const int tx = threadIdx.x & 15, ty = threadIdx.x >> 4;
#pragma unroll
    for (int i = 0; i < 8; i++) {
        const int row = m0 + row_of(i, ty);
#pragma unroll
        for (int jp = 0; jp < 4; jp++) {
            const int col = n0 + col_of(jp, tx);
            float lo, hi; unpack2(acc[i][jp], lo, hi);
            lo += bias[col];
            hi += bias[col + 1];
            if (w == 2) {
                lo = 1.0f / (1.0f + expf(-lo));
                hi = 1.0f / (1.0f + expf(-hi));
            }
            *(float2*)&out[(size_t)row * 256 + col] = make_float2(lo, hi);
        }
    }
}

// Kernel 2: per-(b,i)-slice GEMM ab = a_slice @ b_slice, gated by g.
// grid (4, 512): x = jt + 2*lt, y = slice index (b*256 + i).
extern "C" __global__ void __launch_bounds__(256)
tri_kernel()
{
    const int jt = blockIdx.x & 1, lt = blockIdx.x >> 1;
    const int slice = blockIdx.y;
    const float* A = g_A  + (size_t)slice * 65536;
    const float* B = g_Bp + (size_t)slice * 65536;
    const int m0 = jt * BM, n0 = lt * BN;

    ull acc[8][4];
    gemm128(A, 256, B, 256, m0, n0, 256, acc);

    const int tx = threadIdx.x & 15, ty = threadIdx.x >> 4;
    const size_t base = (size_t)slice * 65536;
#pragma unroll
    for (int i = 0; i < 8; i++) {
        const int row = m0 + row_of(i, ty);
#pragma unroll
        for (int jp = 0; jp < 4; jp++) {
            const int col = n0 + col_of(jp, tx);
            float lo, hi; unpack2(acc[i][jp], lo, hi);
            const size_t idx = base + (size_t)row * 256 + col;
            float2 gv = *(const float2*)&g_G[idx];
            *(float2*)&g_H[idx] = make_float2(lo * gv.x, hi * gv.y);
        }
    }
}

// Kernel 3: out = H @ Wo + bo. grid (2, 1024).
extern "C" __global__ void __launch_bounds__(256)
out_kernel(const float* __restrict__ Wo, const float* __restrict__ bo,
           float* __restrict__ out)
{
    const int m0 = blockIdx.y * BM, n0 = blockIdx.x * BN;

    ull acc[8][4];
    gemm128(g_H, 256, Wo, 256, m0, n0, 256, acc);

    const int tx = threadIdx.x & 15, ty = threadIdx.x >> 4;
#pragma unroll
    for (int i = 0; i < 8; i++) {
        const int row = m0 + row_of(i, ty);
#pragma unroll
        for (int jp = 0; jp < 4; jp++) {
            const int col = n0 + col_of(jp, tx);
            float lo, hi; unpack2(acc[i][jp], lo, hi);
            lo += bo[col];
            hi += bo[col + 1];
            *(float2*)&out[(size_t)row * 256 + col] = make_float2(lo, hi);
        }
    }
}

extern "C" void kernel_launch(void* const* d_in, const int* in_sizes, int n_in,
                              void* d_out, int out_size)
{
    const float* pair = (const float*)d_in[0];
    const float* Wa   = (const float*)d_in[1];
    const float* ba   = (const float*)d_in[2];
    const float* Wb   = (const float*)d_in[3];
    const float* bb   = (const float*)d_in[4];
    const float* Wg   = (const float*)d_in[5];
    const float* bg   = (const float*)d_in[6];
    const float* Wo   = (const float*)d_in[7];
    const float* bo   = (const float*)d_in[8];
    float* out = (float*)d_out;

    proj_kernel<<<dim3(6, 1024), 256>>>(pair, Wa, ba, Wb, bb, Wg, bg);
    tri_kernel <<<dim3(4, 512),  256>>>();
    out_kernel <<<dim3(2, 1024), 256>>>(Wo, bo, out);
}

// round 3
// speedup vs baseline: 1.4983x; 1.4983x over previous
#include <cuda_runtime.h>
#include <cuda_bf16.h>
#include <cstdint>

// TriangleMultiplication via legacy tensor-core path (mma.sync m16n8k16 bf16),
// fp32 emulated by split-bf16 3-pass: A*B ~= Ah*Bh + Ah*Bl + Al*Bh.
//   a = pair@Wa+ba ; b = pair@Wb+bb ; g = sigmoid(pair@Wg+bg)
//   ab[s] = a[s] @ b[s] (512 slice GEMMs) ; out = (g*ab)@Wo + bo
// CTA tile 128x256 (8 warps, warp tile 64x64), K streamed in 4 chunks of 64.
// B operands stored [n][k] (k-contiguous) to match mma row.col.

#define THREADS 256
#define RSTRIDE 144            // smem row pitch bytes: 64 bf16 (128B) + 16 pad
#define SA_H 0
#define SA_L 18432             // 128*144
#define SB_H 36864
#define SB_L 73728             // +256*144
#define SMEM_FILL 110592
#define SMEM_TOTAL 133120      // max(fill, 8 warps * 64*65*4 stage)

#define NELEM 33554432         // 2*256*256*256
static __device__ float g_A[NELEM];      // a proj, natural [m][k]
static __device__ float g_BT[NELEM];     // b proj, per-slice transposed [s][l][j]
static __device__ float g_G[NELEM];      // sigmoid gate, natural [m][l]
static __device__ float g_H[NELEM];      // g * ab, natural [m][l]
static __device__ float g_WT[4 * 65536]; // W^T per weight: WT[d][c] = W[c][d]

__device__ __forceinline__ uint32_t pack_bf2(__nv_bfloat16 x, __nv_bfloat16 y) {
    __nv_bfloat162 t = __halves2bfloat162(x, y);
    return *reinterpret_cast<uint32_t*>(&t);
}

__device__ __forceinline__ void mma16816(float d[4], const uint32_t a[4], const uint32_t b[2]) {
    asm volatile(
        "mma.sync.aligned.m16n8k16.row.col.f32.bf16.bf16.f32 "
        "{%0,%1,%2,%3}, {%4,%5,%6,%7}, {%8,%9}, {%0,%1,%2,%3};"
        : "+f"(d[0]), "+f"(d[1]), "+f"(d[2]), "+f"(d[3])
        : "r"(a[0]), "r"(a[1]), "r"(a[2]), "r"(a[3]), "r"(b[0]), "r"(b[1]));
}

// Fill split hi/lo bf16 smem tiles from fp32 gmem (row stride 256), k window
// [koff, koff+64). rows in {128, 256}.
__device__ __forceinline__ void fill_split(char* sh, char* sl,
                                           const float* __restrict__ src,
                                           int rows, int koff)
{
    const int nf4 = rows * 16;
    for (int i = threadIdx.x; i < nf4; i += THREADS) {
        const int r = i >> 4, seg = i & 15;
        float4 v = *(const float4*)(src + (size_t)r * 256 + koff + seg * 4);
        __nv_bfloat16 h0 = __float2bfloat16_rn(v.x);
        __nv_bfloat16 h1 = __float2bfloat16_rn(v.y);
        __nv_bfloat16 h2 = __float2bfloat16_rn(v.z);
        __nv_bfloat16 h3 = __float2bfloat16_rn(v.w);
        __nv_bfloat16 l0 = __float2bfloat16_rn(v.x - __bfloat162float(h0));
        __nv_bfloat16 l1 = __float2bfloat16_rn(v.y - __bfloat162float(h1));
        __nv_bfloat16 l2 = __float2bfloat16_rn(v.z - __bfloat162float(h2));
        __nv_bfloat16 l3 = __float2bfloat16_rn(v.w - __bfloat162float(h3));
        uint2 H = make_uint2(pack_bf2(h0, h1), pack_bf2(h2, h3));
        uint2 L = make_uint2(pack_bf2(l0, l1), pack_bf2(l2, l3));
        *(uint2*)(sh + r * RSTRIDE + seg * 8) = H;
        *(uint2*)(sl + r * RSTRIDE + seg * 8) = L;
    }
}

// Compute acc[4][8][4] = Asrc[128,256] @ Bsrc[256,256]^T-rows, emulated fp32.
// Asrc row-major [m][k] stride 256; Bsrc [n][k] stride 256 (col-major B).
__device__ __forceinline__ void gemm_compute(char* smem,
                                             const float* __restrict__ Asrc,
                                             const float* __restrict__ Bsrc,
                                             float acc[4][8][4])
{
    const int wid = threadIdx.x >> 5, lane = threadIdx.x & 31;
    const int wm = wid >> 2, wn = wid & 3;          // 2 x 4 warps
    const int g = lane >> 2, qc = lane & 3;

#pragma unroll
    for (int mt = 0; mt < 4; ++mt)
#pragma unroll
        for (int nt = 0; nt < 8; ++nt)
#pragma unroll
            for (int i = 0; i < 4; ++i) acc[mt][nt][i] = 0.f;

    for (int c = 0; c < 4; ++c) {
        fill_split(smem + SA_H, smem + SA_L, Asrc, 128, c * 64);
        fill_split(smem + SB_H, smem + SB_L, Bsrc, 256, c * 64);
        __syncthreads();
#pragma unroll
        for (int s = 0; s < 4; ++s) {
            uint32_t ah[4][4], al[4][4], bh[8][2], bl[8][2];
#pragma unroll
            for (int mt = 0; mt < 4; ++mt) {
                const int base = (wm * 64 + mt * 16 + g) * RSTRIDE + s * 32 + qc * 4;
                ah[mt][0] = *(const uint32_t*)(smem + SA_H + base);
                ah[mt][1] = *(const uint32_t*)(smem + SA_H + base + 8 * RSTRIDE);
                ah[mt][2] = *(const uint32_t*)(smem + SA_H + base + 16);
                ah[mt][3] = *(const uint32_t*)(smem + SA_H + base + 8 * RSTRIDE + 16);
                al[mt][0] = *(const uint32_t*)(smem + SA_L + base);
                al[mt][1] = *(const uint32_t*)(smem + SA_L + base + 8 * RSTRIDE);
                al[mt][2] = *(const uint32_t*)(smem + SA_L + base + 16);
                al[mt][3] = *(const uint32_t*)(smem + SA_L + base + 8 * RSTRIDE + 16);
            }
#pragma unroll
            for (int nt = 0; nt < 8; ++nt) {
                const int base = (wn * 64 + nt * 8 + g) * RSTRIDE + s * 32 + qc * 4;
                bh[nt][0] = *(const uint32_t*)(smem + SB_H + base);
                bh[nt][1] = *(const uint32_t*)(smem + SB_H + base + 16);
                bl[nt][0] = *(const uint32_t*)(smem + SB_L + base);
                bl[nt][1] = *(const uint32_t*)(smem + SB_L + base + 16);
            }
#pragma unroll
            for (int mt = 0; mt < 4; ++mt)
#pragma unroll
                for (int nt = 0; nt < 8; ++nt) {
                    mma16816(acc[mt][nt], ah[mt], bh[nt]);
                    mma16816(acc[mt][nt], ah[mt], bl[nt]);
                    mma16816(acc[mt][nt], al[mt], bh[nt]);
                }
        }
        __syncthreads();
    }
}

// ---------------- kernels ----------------

extern "C" __global__ void wprep_kernel(const float* __restrict__ Wa,
                                        const float* __restrict__ Wb,
                                        const float* __restrict__ Wg,
                                        const float* __restrict__ Wo)
{
    const float* Ws[4] = {Wa, Wb, Wg, Wo};
    const int d = blockIdx.x, c = threadIdx.x;
#pragma unroll
    for (int w = 0; w < 4; ++w)
        g_WT[w * 65536 + d * 256 + c] = Ws[w][c * 256 + d];
}

// grid (3, 1024): x = weight {a,b,g}, y = m-tile (128 rows of 131072).
extern "C" __global__ void __launch_bounds__(THREADS)
proj_kernel(const float* __restrict__ pair,
            const float* __restrict__ ba, const float* __restrict__ bb,
            const float* __restrict__ bg)
{
    extern __shared__ char smem[];
    const int w = blockIdx.x;
    const int m0 = blockIdx.y * 128;

    float acc[4][8][4];
    gemm_compute(smem, pair + (size_t)m0 * 256, g_WT + w * 65536, acc);
    __syncthreads();  // smem reuse for transpose staging

    const float* bias = (w == 0) ? ba : ((w == 1) ? bb : bg);
    const int wid = threadIdx.x >> 5, lane = threadIdx.x & 31;
    const int wm = wid >> 2, wn = wid & 3;
    const int g = lane >> 2, qc = lane & 3;

    if (w == 1) {
        // stage warp tile [64 m][64 n] -> write transposed to g_BT[s][l][j]
        float* stg = (float*)smem + wid * 4160;  // 64*65
#pragma unroll
        for (int mt = 0; mt < 4; ++mt)
#pragma unroll
            for (int nt = 0; nt < 8; ++nt) {
                const int rm = mt * 16 + g, cn = nt * 8 + 2 * qc;
                float2 bv = *(const float2*)(bias + wn * 64 + cn);
                stg[rm * 65 + cn]           = acc[mt][nt][0] + bv.x;
                stg[rm * 65 + cn + 1]       = acc[mt][nt][1] + bv.y;
                stg[(rm + 8) * 65 + cn]     = acc[mt][nt][2] + bv.x;
                stg[(rm + 8) * 65 + cn + 1] = acc[mt][nt][3] + bv.y;
            }
        __syncwarp();
        const int slice = m0 >> 8;
        const int j0 = (m0 & 255) + wm * 64;
        float* dst = g_BT + (size_t)slice * 65536;
        for (int r = 0; r < 64; ++r) {
            float x = stg[(2 * lane) * 65 + r];
            float y = stg[(2 * lane + 1) * 65 + r];
            *(float2*)(dst + (size_t)(wn * 64 + r) * 256 + j0 + 2 * lane) = make_float2(x, y);
        }
    } else {
        float* dst = (w == 0) ? g_A : g_G;
#pragma unroll
        for (int mt = 0; mt < 4; ++mt) {
            const int R0 = m0 + wm * 64 + mt * 16 + g;
#pragma unroll
            for (int nt = 0; nt < 8; ++nt) {
                const int col = wn * 64 + nt * 8 + 2 * qc;
                float2 bv = *(const float2*)(bias + col);
                float v0 = acc[mt][nt][0] + bv.x, v1 = acc[mt][nt][1] + bv.y;
                float v2 = acc[mt][nt][2] + bv.x, v3 = acc[mt][nt][3] + bv.y;
                if (w == 2) {
                    v0 = 1.f / (1.f + __expf(-v0)); v1 = 1.f / (1.f + __expf(-v1));
                    v2 = 1.f / (1.f + __expf(-v2)); v3 = 1.f / (1.f + __expf(-v3));
                }
                *(float2*)(dst + (size_t)R0 * 256 + col)       = make_float2(v0, v1);
                *(float2*)(dst + (size_t)(R0 + 8) * 256 + col) = make_float2(v2, v3);
            }
        }
    }
}

// grid (2, 512): x = j-tile, y = slice. h = g * (a_s @ b_s).
extern "C" __global__ void __launch_bounds__(THREADS)
tri_kernel()
{
    extern __shared__ char smem[];
    const int jt = blockIdx.x, slice = blockIdx.y;

    float acc[4][8][4];
    gemm_compute(smem,
                 g_A + (size_t)slice * 65536 + (size_t)jt * 128 * 256,
                 g_BT + (size_t)slice * 65536, acc);

    const int wid = threadIdx.x >> 5, lane = threadIdx.x & 31;
    const int wm = wid >> 2, wn = wid & 3;
    const int g = lane >> 2, qc = lane & 3;
    const int mbase = slice * 256 + jt * 128 + wm * 64;

#pragma unroll
    for (int mt = 0; mt < 4; ++mt) {
        const int R0 = mbase + mt * 16 + g;
#pragma unroll
        for (int nt = 0; nt < 8; ++nt) {
            const int col = wn * 64 + nt * 8 + 2 * qc;
            float2 g0 = *(const float2*)(g_G + (size_t)R0 * 256 + col);
            float2 g1 = *(const float2*)(g_G + (size_t)(R0 + 8) * 256 + col);
            *(float2*)(g_H + (size_t)R0 * 256 + col) =
                make_float2(acc[mt][nt][0] * g0.x, acc[mt][nt][1] * g0.y);
            *(float2*)(g_H + (size_t)(R0 + 8) * 256 + col) =
                make_float2(acc[mt][nt][2] * g1.x, acc[mt][nt][3] * g1.y);
        }
    }
}

// grid 1024: out = H @ Wo^T-rows + bo.
extern "C" __global__ void __launch_bounds__(THREADS)
out_kernel(const float* __restrict__ bo, float* __restrict__ out)
{
    extern __shared__ char smem[];
    const int m0 = blockIdx.x * 128;

    float acc[4][8][4];
    gemm_compute(smem, g_H + (size_t)m0 * 256, g_WT + 3 * 65536, acc);

    const int wid = threadIdx.x >> 5, lane = threadIdx.x & 31;
    const int wm = wid >> 2, wn = wid & 3;
    const int g = lane >> 2, qc = lane & 3;

#pragma unroll
    for (int mt = 0; mt < 4; ++mt) {
        const int R0 = m0 + wm * 64 + mt * 16 + g;
#pragma unroll
        for (int nt = 0; nt < 8; ++nt) {
            const int col = wn * 64 + nt * 8 + 2 * qc;
            float2 bv = *(const float2*)(bo + col);
            *(float2*)(out + (size_t)R0 * 256 + col) =
                make_float2(acc[mt][nt][0] + bv.x, acc[mt][nt][1] + bv.y);
            *(float2*)(out + (size_t)(R0 + 8) * 256 + col) =
                make_float2(acc[mt][nt][2] + bv.x, acc[mt][nt][3] + bv.y);
        }
    }
}

extern "C" void kernel_launch(void* const* d_in, const int* in_sizes, int n_in,
                              void* d_out, int out_size)
{
    const float* pair = (const float*)d_in[0];
    const float* Wa   = (const float*)d_in[1];
    const float* ba   = (const float*)d_in[2];
    const float* Wb   = (const float*)d_in[3];
    const float* bb   = (const float*)d_in[4];
    const float* Wg   = (const float*)d_in[5];
    const float* bg   = (const float*)d_in[6];
    const float* Wo   = (const float*)d_in[7];
    const float* bo   = (const float*)d_in[8];
    float* out = (float*)d_out;

    cudaFuncSetAttribute(proj_kernel, cudaFuncAttributeMaxDynamicSharedMemorySize, SMEM_TOTAL);
    cudaFuncSetAttribute(tri_kernel,  cudaFuncAttributeMaxDynamicSharedMemorySize, SMEM_TOTAL);
    cudaFuncSetAttribute(out_kernel,  cudaFuncAttributeMaxDynamicSharedMemorySize, SMEM_TOTAL);

    wprep_kernel<<<256, 256>>>(Wa, Wb, Wg, Wo);
    proj_kernel<<<dim3(3, 1024), THREADS, SMEM_TOTAL>>>(pair, ba, bb, bg);
    tri_kernel <<<dim3(2, 512),  THREADS, SMEM_TOTAL>>>();
    out_kernel <<<1024,          THREADS, SMEM_TOTAL>>>(bo, out);
}

// round 4
// speedup vs baseline: 2.0655x; 1.3786x over previous
#include <cuda_runtime.h>
#include <cuda_bf16.h>
#include <cstdint>

// TriangleMultiplication, legacy tensor cores (mma.sync m16n8k16 bf16),
// fp32 emulated via split-bf16 3-pass: A*B ~= Ah*Bh + Ah*Bl + Al*Bh.
// R4: operands pre-split into bf16 hi/lo gmem planes; mainloops use
// cp.async double-buffered pipeline + ldmatrix fragment loads over
// XOR-swizzled 128B smem rows.

#define THREADS 256
#define STAGE   98304
#define OFF_AH  0
#define OFF_AL  16384
#define OFF_BH  32768
#define OFF_BL  65536
#define SMEM_TOTAL 196608

#define NELEM 33554432  // 2*256*256*256

// split planes (bf16): pair, a-proj, b-proj(transposed per slice), h
static __device__ __align__(16) __nv_bfloat16 g_Ph[NELEM], g_Pl[NELEM];
static __device__ __align__(16) __nv_bfloat16 g_Ah[NELEM], g_Al[NELEM];
static __device__ __align__(16) __nv_bfloat16 g_Bh[NELEM], g_Bl[NELEM];
static __device__ __align__(16) __nv_bfloat16 g_Hh[NELEM], g_Hl[NELEM];
static __device__ __align__(16) __nv_bfloat16 g_Wh[4*65536], g_Wl[4*65536]; // W^T planes
static __device__ float g_G[NELEM];  // sigmoid gate, fp32 natural [m][l]

__device__ __forceinline__ uint32_t pack_bf2(__nv_bfloat16 x, __nv_bfloat16 y) {
    __nv_bfloat162 t = __halves2bfloat162(x, y);
    return *reinterpret_cast<uint32_t*>(&t);
}
__device__ __forceinline__ uint32_t smem_u32(const void* p) {
    uint32_t a;
    asm("{ .reg .u64 t; cvta.to.shared.u64 t, %1; cvt.u32.u64 %0, t; }" : "=r"(a) : "l"(p));
    return a;
}
__device__ __forceinline__ void mma16816(float d[4], const uint32_t a[4], const uint32_t b[2]) {
    asm volatile(
        "mma.sync.aligned.m16n8k16.row.col.f32.bf16.bf16.f32 "
        "{%0,%1,%2,%3}, {%4,%5,%6,%7}, {%8,%9}, {%0,%1,%2,%3};"
        : "+f"(d[0]), "+f"(d[1]), "+f"(d[2]), "+f"(d[3])
        : "r"(a[0]), "r"(a[1]), "r"(a[2]), "r"(a[3]), "r"(b[0]), "r"(b[1]));
}
__device__ __forceinline__ void ldsm_x4(uint32_t r[4], uint32_t a) {
    asm volatile("ldmatrix.sync.aligned.m8n8.x4.shared.b16 {%0,%1,%2,%3}, [%4];"
        : "=r"(r[0]), "=r"(r[1]), "=r"(r[2]), "=r"(r[3]) : "r"(a));
}
__device__ __forceinline__ void ldsm_x2(uint32_t r[2], uint32_t a) {
    asm volatile("ldmatrix.sync.aligned.m8n8.x2.shared.b16 {%0,%1}, [%2];"
        : "=r"(r[0]), "=r"(r[1]) : "r"(a));
}
__device__ __forceinline__ void cpa(uint32_t d, const void* s) {
    asm volatile("cp.async.cg.shared.global [%0], [%1], 16;" :: "r"(d), "l"(s));
}
__device__ __forceinline__ void split2(float x, float y, uint32_t& H, uint32_t& L) {
    __nv_bfloat16 hx = __float2bfloat16_rn(x), hy = __float2bfloat16_rn(y);
    __nv_bfloat16 lx = __float2bfloat16_rn(x - __bfloat162float(hx));
    __nv_bfloat16 ly = __float2bfloat16_rn(y - __bfloat162float(hy));
    H = pack_bf2(hx, hy); L = pack_bf2(lx, ly);
}

// Fill ROWS x 64-bf16 (128B rows, XOR swizzle) from plane src (row stride
// 256 elems), k window [koff, koff+64).
template<int ROWS>
__device__ __forceinline__ void fill_plane(uint32_t dst,
                                           const __nv_bfloat16* __restrict__ src,
                                           int koff)
{
#pragma unroll
    for (int t = 0; t < ROWS*8/THREADS; ++t) {
        const int i = t*THREADS + threadIdx.x;
        const int r = i >> 3, ch = i & 7;
        const uint32_t o = (uint32_t)(r*128) + (uint32_t)((ch ^ (r & 7)) * 16);
        cpa(dst + o, src + (size_t)r*256 + koff + ch*8);
    }
}

__device__ __forceinline__ void issue_chunk(uint32_t buf,
    const __nv_bfloat16* Ah, const __nv_bfloat16* Al,
    const __nv_bfloat16* Bh, const __nv_bfloat16* Bl, int koff)
{
    fill_plane<128>(buf + OFF_AH, Ah, koff);
    fill_plane<128>(buf + OFF_AL, Al, koff);
    fill_plane<256>(buf + OFF_BH, Bh, koff);
    fill_plane<256>(buf + OFF_BL, Bl, koff);
    asm volatile("cp.async.commit_group;" ::: "memory");
}

// acc[4][8][4] = A[128,256] @ B[256,256]^T-rows (planes, row stride 256).
__device__ __forceinline__ void gemm_compute(uint32_t sb,
    const __nv_bfloat16* __restrict__ Ah, const __nv_bfloat16* __restrict__ Al,
    const __nv_bfloat16* __restrict__ Bh, const __nv_bfloat16* __restrict__ Bl,
    float acc[4][8][4])
{
    const int lane = threadIdx.x & 31, wid = threadIdx.x >> 5;
    const int wm = wid >> 2, wn = wid & 3;  // 2 x 4 warps, warp tile 64x64

#pragma unroll
    for (int mt = 0; mt < 4; ++mt)
#pragma unroll
        for (int nt = 0; nt < 8; ++nt)
#pragma unroll
            for (int i = 0; i < 4; ++i) acc[mt][nt][i] = 0.f;

    issue_chunk(sb,         Ah, Al, Bh, Bl, 0);
    issue_chunk(sb + STAGE, Ah, Al, Bh, Bl, 64);

    const uint32_t a_row  = ((lane >> 3) & 1) * 8 + (lane & 7);
    const uint32_t a_base = (wm*64 + a_row) * 128;
    const uint32_t a_kh   = lane >> 4;
    const uint32_t b_base = (wn*64 + (lane & 7)) * 128;
    const uint32_t b_kh   = (lane >> 3) & 1;
    const uint32_t xr     = lane & 7;

#pragma unroll
    for (int c = 0; c < 4; ++c) {
        if (c < 3) asm volatile("cp.async.wait_group 1;" ::: "memory");
        else       asm volatile("cp.async.wait_group 0;" ::: "memory");
        __syncthreads();
        const uint32_t buf = sb + (uint32_t)(c & 1) * STAGE;
#pragma unroll
        for (int s = 0; s < 4; ++s) {
            uint32_t ah[4][4], al[4][4], bh[8][2], bl[8][2];
            const uint32_t ax = (((uint32_t)s*2 + a_kh) ^ xr) * 16;
            const uint32_t bx = (((uint32_t)s*2 + b_kh) ^ xr) * 16;
#pragma unroll
            for (int mt = 0; mt < 4; ++mt) {
                const uint32_t ao = buf + a_base + mt*2048 + ax;
                ldsm_x4(ah[mt], ao + OFF_AH);
                ldsm_x4(al[mt], ao + OFF_AL);
            }
#pragma unroll
            for (int nt = 0; nt < 8; ++nt) {
                const uint32_t bo = buf + b_base + nt*1024 + bx;
                ldsm_x2(bh[nt], bo + OFF_BH);
                ldsm_x2(bl[nt], bo + OFF_BL);
            }
#pragma unroll
            for (int mt = 0; mt < 4; ++mt)
#pragma unroll
                for (int nt = 0; nt < 8; ++nt) {
                    mma16816(acc[mt][nt], ah[mt], bh[nt]);
                    mma16816(acc[mt][nt], ah[mt], bl[nt]);
                    mma16816(acc[mt][nt], al[mt], bh[nt]);
                }
        }
        __syncthreads();
        if (c < 2)
            issue_chunk(sb + (uint32_t)(c & 1) * STAGE, Ah, Al, Bh, Bl, (c + 2) * 64);
    }
}

// ---------------- prep kernels ----------------

// Split pair fp32 -> bf16 hi/lo planes. grid 32768 x 256 thr, 4 elems/thread.
extern "C" __global__ void psplit_kernel(const float* __restrict__ pair)
{
    const size_t i = ((size_t)blockIdx.x * 256 + threadIdx.x) * 4;
    float4 v = *(const float4*)(pair + i);
    uint32_t H0, L0, H1, L1;
    split2(v.x, v.y, H0, L0);
    split2(v.z, v.w, H1, L1);
    *(uint2*)(g_Ph + i) = make_uint2(H0, H1);
    *(uint2*)(g_Pl + i) = make_uint2(L0, L1);
}

// Transpose + split the 4 weights: planes [w][d][c] = W_w[c][d].
extern "C" __global__ void wprep_kernel(const float* __restrict__ Wa,
                                        const float* __restrict__ Wb,
                                        const float* __restrict__ Wg,
                                        const float* __restrict__ Wo)
{
    const float* Ws[4] = {Wa, Wb, Wg, Wo};
    const int d = blockIdx.x, c = threadIdx.x;
#pragma unroll
    for (int w = 0; w < 4; ++w) {
        float v = Ws[w][c*256 + d];
        __nv_bfloat16 h = __float2bfloat16_rn(v);
        __nv_bfloat16 l = __float2bfloat16_rn(v - __bfloat162float(h));
        g_Wh[w*65536 + d*256 + c] = h;
        g_Wl[w*65536 + d*256 + c] = l;
    }
}

// ---------------- GEMM kernels ----------------

// grid (3, 1024): x = weight {a,b,g}, y = m-tile of 128 rows.
extern "C" __global__ void __launch_bounds__(THREADS)
proj_kernel(const float* __restrict__ ba, const float* __restrict__ bb,
            const float* __restrict__ bg)
{
    extern __shared__ char smem[];
    const uint32_t sb = smem_u32(smem);
    const int w = blockIdx.x;
    const int m0 = blockIdx.y * 128;

    float acc[4][8][4];
    gemm_compute(sb, g_Ph + (size_t)m0*256, g_Pl + (size_t)m0*256,
                 g_Wh + w*65536, g_Wl + w*65536, acc);
    __syncthreads();

    const float* bias = (w == 0) ? ba : ((w == 1) ? bb : bg);
    const int wid = threadIdx.x >> 5, lane = threadIdx.x & 31;
    const int wm = wid >> 2, wn = wid & 3;
    const int g = lane >> 2, qc = lane & 3;

    if (w == 1) {
        // stage warp tile [64 m][64 n] fp32, then write transposed split planes
        float* stg = (float*)smem + wid * 4160;  // 64*65
#pragma unroll
        for (int mt = 0; mt < 4; ++mt)
#pragma unroll
            for (int nt = 0; nt < 8; ++nt) {
                const int rm = mt*16 + g, cn = nt*8 + 2*qc;
                float2 bv = *(const float2*)(bias + wn*64 + cn);
                stg[rm*65 + cn]           = acc[mt][nt][0] + bv.x;
                stg[rm*65 + cn + 1]       = acc[mt][nt][1] + bv.y;
                stg[(rm + 8)*65 + cn]     = acc[mt][nt][2] + bv.x;
                stg[(rm + 8)*65 + cn + 1] = acc[mt][nt][3] + bv.y;
            }
        __syncwarp();
        const int slice = m0 >> 8;
        const int j0 = (m0 & 255) + wm * 64;
        const size_t sbase = (size_t)slice * 65536;
        for (int r = 0; r < 64; ++r) {
            float x = stg[(2*lane)*65 + r];
            float y = stg[(2*lane + 1)*65 + r];
            uint32_t H, L; split2(x, y, H, L);
            const size_t idx = sbase + (size_t)(wn*64 + r)*256 + j0 + 2*lane;
            *(uint32_t*)(g_Bh + idx) = H;
            *(uint32_t*)(g_Bl + idx) = L;
        }
    } else {
#pragma unroll
        for (int mt = 0; mt < 4; ++mt) {
            const int R0 = m0 + wm*64 + mt*16 + g;
#pragma unroll
            for (int nt = 0; nt < 8; ++nt) {
                const int col = wn*64 + nt*8 + 2*qc;
                float2 bv = *(const float2*)(bias + col);
                float v0 = acc[mt][nt][0] + bv.x, v1 = acc[mt][nt][1] + bv.y;
                float v2 = acc[mt][nt][2] + bv.x, v3 = acc[mt][nt][3] + bv.y;
                if (w == 2) {
                    v0 = 1.f/(1.f + __expf(-v0)); v1 = 1.f/(1.f + __expf(-v1));
                    v2 = 1.f/(1.f + __expf(-v2)); v3 = 1.f/(1.f + __expf(-v3));
                    *(float2*)(g_G + (size_t)R0*256 + col)       = make_float2(v0, v1);
                    *(float2*)(g_G + (size_t)(R0 + 8)*256 + col) = make_float2(v2, v3);
                } else {
                    uint32_t H, L;
                    split2(v0, v1, H, L);
                    *(uint32_t*)(g_Ah + (size_t)R0*256 + col) = H;
                    *(uint32_t*)(g_Al + (size_t)R0*256 + col) = L;
                    split2(v2, v3, H, L);
                    *(uint32_t*)(g_Ah + (size_t)(R0 + 8)*256 + col) = H;
                    *(uint32_t*)(g_Al + (size_t)(R0 + 8)*256 + col) = L;
                }
            }
        }
    }
}

// grid (2, 512): x = j-tile, y = slice. h = g * (a_s @ b_s), split-stored.
extern "C" __global__ void __launch_bounds__(THREADS)
tri_kernel()
{
    extern __shared__ char smem[];
    const uint32_t sb = smem_u32(smem);
    const int jt = blockIdx.x, slice = blockIdx.y;
    const size_t abase = (size_t)slice*65536 + (size_t)jt*128*256;
    const size_t bbase = (size_t)slice*65536;

    float acc[4][8][4];
    gemm_compute(sb, g_Ah + abase, g_Al + abase, g_Bh + bbase, g_Bl + bbase, acc);

    const int wid = threadIdx.x >> 5, lane = threadIdx.x & 31;
    const int wm = wid >> 2, wn = wid & 3;
    const int g = lane >> 2, qc = lane & 3;
    const int mbase = slice*256 + jt*128 + wm*64;

#pragma unroll
    for (int mt = 0; mt < 4; ++mt) {
        const int R0 = mbase + mt*16 + g;
#pragma unroll
        for (int nt = 0; nt < 8; ++nt) {
            const int col = wn*64 + nt*8 + 2*qc;
            float2 g0 = *(const float2*)(g_G + (size_t)R0*256 + col);
            float2 g1 = *(const float2*)(g_G + (size_t)(R0 + 8)*256 + col);
            uint32_t H, L;
            split2(acc[mt][nt][0]*g0.x, acc[mt][nt][1]*g0.y, H, L);
            *(uint32_t*)(g_Hh + (size_t)R0*256 + col) = H;
            *(uint32_t*)(g_Hl + (size_t)R0*256 + col) = L;
            split2(acc[mt][nt][2]*g1.x, acc[mt][nt][3]*g1.y, H, L);
            *(uint32_t*)(g_Hh + (size_t)(R0 + 8)*256 + col) = H;
            *(uint32_t*)(g_Hl + (size_t)(R0 + 8)*256 + col) = L;
        }
    }
}

// grid 1024: out = H @ Wo^T-rows + bo.
extern "C" __global__ void __launch_bounds__(THREADS)
out_kernel(const float* __restrict__ bo, float* __restrict__ out)
{
    extern __shared__ char smem[];
    const uint32_t sb = smem_u32(smem);
    const int m0 = blockIdx.x * 128;

    float acc[4][8][4];
    gemm_compute(sb, g_Hh + (size_t)m0*256, g_Hl + (size_t)m0*256,
                 g_Wh + 3*65536, g_Wl + 3*65536, acc);

    const int wid = threadIdx.x >> 5, lane = threadIdx.x & 31;
    const int wm = wid >> 2, wn = wid & 3;
    const int g = lane >> 2, qc = lane & 3;

#pragma unroll
    for (int mt = 0; mt < 4; ++mt) {
        const int R0 = m0 + wm*64 + mt*16 + g;
#pragma unroll
        for (int nt = 0; nt < 8; ++nt) {
            const int col = wn*64 + nt*8 + 2*qc;
            float2 bv = *(const float2*)(bo + col);
            *(float2*)(out + (size_t)R0*256 + col) =
                make_float2(acc[mt][nt][0] + bv.x, acc[mt][nt][1] + bv.y);
            *(float2*)(out + (size_t)(R0 + 8)*256 + col) =
                make_float2(acc[mt][nt][2] + bv.x, acc[mt][nt][3] + bv.y);
        }
    }
}

extern "C" void kernel_launch(void* const* d_in, const int* in_sizes, int n_in,
                              void* d_out, int out_size)
{
    const float* pair = (const float*)d_in[0];
    const float* Wa   = (const float*)d_in[1];
    const float* ba   = (const float*)d_in[2];
    const float* Wb   = (const float*)d_in[3];
    const float* bb   = (const float*)d_in[4];
    const float* Wg   = (const float*)d_in[5];
    const float* bg   = (const float*)d_in[6];
    const float* Wo   = (const float*)d_in[7];
    const float* bo   = (const float*)d_in[8];
    float* out = (float*)d_out;

    cudaFuncSetAttribute(proj_kernel, cudaFuncAttributeMaxDynamicSharedMemorySize, SMEM_TOTAL);
    cudaFuncSetAttribute(tri_kernel,  cudaFuncAttributeMaxDynamicSharedMemorySize, SMEM_TOTAL);
    cudaFuncSetAttribute(out_kernel,  cudaFuncAttributeMaxDynamicSharedMemorySize, SMEM_TOTAL);

    wprep_kernel <<<256,   256>>>(Wa, Wb, Wg, Wo);
    psplit_kernel<<<32768, 256>>>(pair);
    proj_kernel<<<dim3(3, 1024), THREADS, SMEM_TOTAL>>>(ba, bb, bg);
    tri_kernel <<<dim3(2, 512),  THREADS, SMEM_TOTAL>>>();
    out_kernel <<<1024,          THREADS, SMEM_TOTAL>>>(bo, out);
}

// round 5
// speedup vs baseline: 2.1675x; 1.0494x over previous
#include <cuda_runtime.h>
#include <cuda_bf16.h>
#include <cstdint>

// TriangleMultiplication, mma.sync m16n8k16 bf16, split-bf16 3-pass fp32 emu.
// R5: 512-thread CTAs (16 warps, 4/SMSP), warp tile 32x64, B-frag halves to
// keep regs < 128 (no spills), ldmatrix.x4 for B, cp.async 2-stage pipeline.

#define THREADS 512
#define STAGE   98304
#define OFF_AH  0
#define OFF_AL  16384
#define OFF_BH  32768
#define OFF_BL  65536
#define SMEM_TOTAL 196608

#define NELEM 33554432  // 2*256*256*256

static __device__ __align__(16) __nv_bfloat16 g_Ph[NELEM], g_Pl[NELEM];
static __device__ __align__(16) __nv_bfloat16 g_Ah[NELEM], g_Al[NELEM];
static __device__ __align__(16) __nv_bfloat16 g_Bh[NELEM], g_Bl[NELEM];
static __device__ __align__(16) __nv_bfloat16 g_Hh[NELEM], g_Hl[NELEM];
static __device__ __align__(16) __nv_bfloat16 g_Wh[4*65536], g_Wl[4*65536];
static __device__ float g_G[NELEM];  // sigmoid gate fp32 [m][l]

__device__ __forceinline__ uint32_t pack_bf2(__nv_bfloat16 x, __nv_bfloat16 y) {
    __nv_bfloat162 t = __halves2bfloat162(x, y);
    return *reinterpret_cast<uint32_t*>(&t);
}
__device__ __forceinline__ uint32_t smem_u32(const void* p) {
    uint32_t a;
    asm("{ .reg .u64 t; cvta.to.shared.u64 t, %1; cvt.u32.u64 %0, t; }" : "=r"(a) : "l"(p));
    return a;
}
__device__ __forceinline__ void mma16816(float d[4], const uint32_t a[4], const uint32_t b[2]) {
    asm volatile(
        "mma.sync.aligned.m16n8k16.row.col.f32.bf16.bf16.f32 "
        "{%0,%1,%2,%3}, {%4,%5,%6,%7}, {%8,%9}, {%0,%1,%2,%3};"
        : "+f"(d[0]), "+f"(d[1]), "+f"(d[2]), "+f"(d[3])
        : "r"(a[0]), "r"(a[1]), "r"(a[2]), "r"(a[3]), "r"(b[0]), "r"(b[1]));
}
__device__ __forceinline__ void ldsm_x4(uint32_t r[4], uint32_t a) {
    asm volatile("ldmatrix.sync.aligned.m8n8.x4.shared.b16 {%0,%1,%2,%3}, [%4];"
        : "=r"(r[0]), "=r"(r[1]), "=r"(r[2]), "=r"(r[3]) : "r"(a));
}
__device__ __forceinline__ void cpa(uint32_t d, const void* s) {
    asm volatile("cp.async.cg.shared.global [%0], [%1], 16;" :: "r"(d), "l"(s));
}
__device__ __forceinline__ void split2(float x, float y, uint32_t& H, uint32_t& L) {
    __nv_bfloat16 hx = __float2bfloat16_rn(x), hy = __float2bfloat16_rn(y);
    __nv_bfloat16 lx = __float2bfloat16_rn(x - __bfloat162float(hx));
    __nv_bfloat16 ly = __float2bfloat16_rn(y - __bfloat162float(hy));
    H = pack_bf2(hx, hy); L = pack_bf2(lx, ly);
}

// ROWS x 64 bf16 (128B rows, XOR-swizzled 16B chunks), src row stride 256.
template<int ROWS>
__device__ __forceinline__ void fill_plane(uint32_t dst,
                                           const __nv_bfloat16* __restrict__ src,
                                           int koff)
{
#pragma unroll
    for (int t = 0; t < ROWS*8/THREADS; ++t) {
        const int i = t*THREADS + threadIdx.x;
        const int r = i >> 3, ch = i & 7;
        const uint32_t o = (uint32_t)(r*128) + (uint32_t)((ch ^ (r & 7)) * 16);
        cpa(dst + o, src + (size_t)r*256 + koff + ch*8);
    }
}

__device__ __forceinline__ void issue_chunk(uint32_t buf,
    const __nv_bfloat16* Ah, const __nv_bfloat16* Al,
    const __nv_bfloat16* Bh, const __nv_bfloat16* Bl, int koff)
{
    fill_plane<128>(buf + OFF_AH, Ah, koff);
    fill_plane<128>(buf + OFF_AL, Al, koff);
    fill_plane<256>(buf + OFF_BH, Bh, koff);
    fill_plane<256>(buf + OFF_BL, Bl, koff);
    asm volatile("cp.async.commit_group;" ::: "memory");
}

// acc[2][8][4]: warp tile 32x64 of C = A[128,256] @ B[256,256]^T-rows.
// 16 warps: wm = wid>>2 (m-tiles of 32), wn = wid&3 (n-tiles of 64).
__device__ __forceinline__ void gemm_compute(uint32_t sb,
    const __nv_bfloat16* __restrict__ Ah, const __nv_bfloat16* __restrict__ Al,
    const __nv_bfloat16* __restrict__ Bh, const __nv_bfloat16* __restrict__ Bl,
    float acc[2][8][4])
{
    const int lane = threadIdx.x & 31, wid = threadIdx.x >> 5;
    const int wm = wid >> 2, wn = wid & 3;

#pragma unroll
    for (int mt = 0; mt < 2; ++mt)
#pragma unroll
        for (int nt = 0; nt < 8; ++nt)
#pragma unroll
            for (int i = 0; i < 4; ++i) acc[mt][nt][i] = 0.f;

    issue_chunk(sb,         Ah, Al, Bh, Bl, 0);
    issue_chunk(sb + STAGE, Ah, Al, Bh, Bl, 64);

    const uint32_t xr     = lane & 7;
    const uint32_t a_base = (uint32_t)(wm*32 + (lane & 15)) * 128;
    const uint32_t a_kh   = lane >> 4;
    const uint32_t b_row  = (lane & 7) + ((lane & 16) >> 1);   // row within nt-pair
    const uint32_t b_base = (uint32_t)(wn*64) * 128 + b_row * 128;
    const uint32_t b_kh   = (lane >> 3) & 1;

#pragma unroll
    for (int c = 0; c < 4; ++c) {
        if (c < 3) asm volatile("cp.async.wait_group 1;" ::: "memory");
        else       asm volatile("cp.async.wait_group 0;" ::: "memory");
        __syncthreads();
        const uint32_t buf = sb + (uint32_t)(c & 1) * STAGE;
#pragma unroll
        for (int s = 0; s < 4; ++s) {
            const uint32_t ax = (((uint32_t)s*2 + a_kh) ^ xr) * 16;
            const uint32_t bx = (((uint32_t)s*2 + b_kh) ^ xr) * 16;
            uint32_t ah[2][4], al[2][4];
#pragma unroll
            for (int mt = 0; mt < 2; ++mt) {
                const uint32_t ao = buf + a_base + (uint32_t)mt*2048 + ax;
                ldsm_x4(ah[mt], ao + OFF_AH);
                ldsm_x4(al[mt], ao + OFF_AL);
            }
#pragma unroll
            for (int half = 0; half < 2; ++half) {   // nt-halves limit live regs
                uint32_t bh[2][4], bl[2][4];          // each x4 = two n8 tiles
#pragma unroll
                for (int p = 0; p < 2; ++p) {
                    const uint32_t bo = buf + b_base + (uint32_t)(half*2 + p)*2048 + bx;
                    ldsm_x4(bh[p], bo + OFF_BH);
                    ldsm_x4(bl[p], bo + OFF_BL);
                }
#pragma unroll
                for (int mt = 0; mt < 2; ++mt)
#pragma unroll
                    for (int p = 0; p < 2; ++p)
#pragma unroll
                        for (int q = 0; q < 2; ++q) {
                            const int nt = half*4 + p*2 + q;
                            mma16816(acc[mt][nt], ah[mt], &bh[p][q*2]);
                            mma16816(acc[mt][nt], ah[mt], &bl[p][q*2]);
                            mma16816(acc[mt][nt], al[mt], &bh[p][q*2]);
                        }
            }
        }
        __syncthreads();
        if (c < 2)
            issue_chunk(sb + (uint32_t)(c & 1) * STAGE, Ah, Al, Bh, Bl, (c + 2) * 64);
    }
}

// ---------------- prep kernels ----------------

extern "C" __global__ void psplit_kernel(const float* __restrict__ pair)
{
    const size_t i = ((size_t)blockIdx.x * 256 + threadIdx.x) * 4;
    float4 v = *(const float4*)(pair + i);
    uint32_t H0, L0, H1, L1;
    split2(v.x, v.y, H0, L0);
    split2(v.z, v.w, H1, L1);
    *(uint2*)(g_Ph + i) = make_uint2(H0, H1);
    *(uint2*)(g_Pl + i) = make_uint2(L0, L1);
}

extern "C" __global__ void wprep_kernel(const float* __restrict__ Wa,
                                        const float* __restrict__ Wb,
                                        const float* __restrict__ Wg,
                                        const float* __restrict__ Wo)
{
    const float* Ws[4] = {Wa, Wb, Wg, Wo};
    const int d = blockIdx.x, c = threadIdx.x;
#pragma unroll
    for (int w = 0; w < 4; ++w) {
        float v = Ws[w][c*256 + d];
        __nv_bfloat16 h = __float2bfloat16_rn(v);
        __nv_bfloat16 l = __float2bfloat16_rn(v - __bfloat162float(h));
        g_Wh[w*65536 + d*256 + c] = h;
        g_Wl[w*65536 + d*256 + c] = l;
    }
}

// ---------------- GEMM kernels ----------------

// grid (3, 1024): x = weight {a,b,g}, y = m-tile of 128 rows.
extern "C" __global__ void __launch_bounds__(THREADS)
proj_kernel(const float* __restrict__ ba, const float* __restrict__ bb,
            const float* __restrict__ bg)
{
    extern __shared__ char smem[];
    const uint32_t sb = smem_u32(smem);
    const int w = blockIdx.x;
    const int m0 = blockIdx.y * 128;

    float acc[2][8][4];
    gemm_compute(sb, g_Ph + (size_t)m0*256, g_Pl + (size_t)m0*256,
                 g_Wh + w*65536, g_Wl + w*65536, acc);
    __syncthreads();

    const float* bias = (w == 0) ? ba : ((w == 1) ? bb : bg);
    const int wid = threadIdx.x >> 5, lane = threadIdx.x & 31;
    const int wm = wid >> 2, wn = wid & 3;
    const int g = lane >> 2, qc = lane & 3;

    if (w == 1) {
        // stage warp tile [32 m][64 n] fp32 -> transposed split-plane store
        float* stg = (float*)smem + wid * 2080;  // 32*65
#pragma unroll
        for (int mt = 0; mt < 2; ++mt)
#pragma unroll
            for (int nt = 0; nt < 8; ++nt) {
                const int rm = mt*16 + g, cn = nt*8 + 2*qc;
                float2 bv = *(const float2*)(bias + wn*64 + cn);
                stg[rm*65 + cn]           = acc[mt][nt][0] + bv.x;
                stg[rm*65 + cn + 1]       = acc[mt][nt][1] + bv.y;
                stg[(rm + 8)*65 + cn]     = acc[mt][nt][2] + bv.x;
                stg[(rm + 8)*65 + cn + 1] = acc[mt][nt][3] + bv.y;
            }
        __syncwarp();
        const int slice = m0 >> 8;
        const int j0 = (m0 & 255) + wm * 32;
        const int m2 = 2 * (lane & 15);
        const size_t sbase = (size_t)slice * 65536;
        for (int r = lane >> 4; r < 64; r += 2) {
            float x = stg[m2*65 + r];
            float y = stg[(m2 + 1)*65 + r];
            uint32_t H, L; split2(x, y, H, L);
            const size_t idx = sbase + (size_t)(wn*64 + r)*256 + j0 + m2;
            *(uint32_t*)(g_Bh + idx) = H;
            *(uint32_t*)(g_Bl + idx) = L;
        }
    } else {
#pragma unroll
        for (int mt = 0; mt < 2; ++mt) {
            const int R0 = m0 + wm*32 + mt*16 + g;
#pragma unroll
            for (int nt = 0; nt < 8; ++nt) {
                const int col = wn*64 + nt*8 + 2*qc;
                float2 bv = *(const float2*)(bias + col);
                float v0 = acc[mt][nt][0] + bv.x, v1 = acc[mt][nt][1] + bv.y;
                float v2 = acc[mt][nt][2] + bv.x, v3 = acc[mt][nt][3] + bv.y;
                if (w == 2) {
                    v0 = 1.f/(1.f + __expf(-v0)); v1 = 1.f/(1.f + __expf(-v1));
                    v2 = 1.f/(1.f + __expf(-v2)); v3 = 1.f/(1.f + __expf(-v3));
                    *(float2*)(g_G + (size_t)R0*256 + col)       = make_float2(v0, v1);
                    *(float2*)(g_G + (size_t)(R0 + 8)*256 + col) = make_float2(v2, v3);
                } else {
                    uint32_t H, L;
                    split2(v0, v1, H, L);
                    *(uint32_t*)(g_Ah + (size_t)R0*256 + col) = H;
                    *(uint32_t*)(g_Al + (size_t)R0*256 + col) = L;
                    split2(v2, v3, H, L);
                    *(uint32_t*)(g_Ah + (size_t)(R0 + 8)*256 + col) = H;
                    *(uint32_t*)(g_Al + (size_t)(R0 + 8)*256 + col) = L;
                }
            }
        }
    }
}

// grid (2, 512): x = j-tile, y = slice. h = g * (a_s @ b_s), split-stored.
extern "C" __global__ void __launch_bounds__(THREADS)
tri_kernel()
{
    extern __shared__ char smem[];
    const uint32_t sb = smem_u32(smem);
    const int jt = blockIdx.x, slice = blockIdx.y;
    const size_t abase = (size_t)slice*65536 + (size_t)jt*128*256;
    const size_t bbase = (size_t)slice*65536;

    float acc[2][8][4];
    gemm_compute(sb, g_Ah + abase, g_Al + abase, g_Bh + bbase, g_Bl + bbase, acc);

    const int wid = threadIdx.x >> 5, lane = threadIdx.x & 31;
    const int wm = wid >> 2, wn = wid & 3;
    const int g = lane >> 2, qc = lane & 3;
    const int mbase = slice*256 + jt*128 + wm*32;

#pragma unroll
    for (int mt = 0; mt < 2; ++mt) {
        const int R0 = mbase + mt*16 + g;
#pragma unroll
        for (int nt = 0; nt < 8; ++nt) {
            const int col = wn*64 + nt*8 + 2*qc;
            float2 g0 = *(const float2*)(g_G + (size_t)R0*256 + col);
            float2 g1 = *(const float2*)(g_G + (size_t)(R0 + 8)*256 + col);
            uint32_t H, L;
            split2(acc[mt][nt][0]*g0.x, acc[mt][nt][1]*g0.y, H, L);
            *(uint32_t*)(g_Hh + (size_t)R0*256 + col) = H;
            *(uint32_t*)(g_Hl + (size_t)R0*256 + col) = L;
            split2(acc[mt][nt][2]*g1.x, acc[mt][nt][3]*g1.y, H, L);
            *(uint32_t*)(g_Hh + (size_t)(R0 + 8)*256 + col) = H;
            *(uint32_t*)(g_Hl + (size_t)(R0 + 8)*256 + col) = L;
        }
    }
}

// grid 1024: out = H @ Wo^T-rows + bo.
extern "C" __global__ void __launch_bounds__(THREADS)
out_kernel(const float* __restrict__ bo, float* __restrict__ out)
{
    extern __shared__ char smem[];
    const uint32_t sb = smem_u32(smem);
    const int m0 = blockIdx.x * 128;

    float acc[2][8][4];
    gemm_compute(sb, g_Hh + (size_t)m0*256, g_Hl + (size_t)m0*256,
                 g_Wh + 3*65536, g_Wl + 3*65536, acc);

    const int wid = threadIdx.x >> 5, lane = threadIdx.x & 31;
    const int wm = wid >> 2, wn = wid & 3;
    const int g = lane >> 2, qc = lane & 3;

#pragma unroll
    for (int mt = 0; mt < 2; ++mt) {
        const int R0 = m0 + wm*32 + mt*16 + g;
#pragma unroll
        for (int nt = 0; nt < 8; ++nt) {
            const int col = wn*64 + nt*8 + 2*qc;
            float2 bv = *(const float2*)(bo + col);
            *(float2*)(out + (size_t)R0*256 + col) =
                make_float2(acc[mt][nt][0] + bv.x, acc[mt][nt][1] + bv.y);
            *(float2*)(out + (size_t)(R0 + 8)*256 + col) =
                make_float2(acc[mt][nt][2] + bv.x, acc[mt][nt][3] + bv.y);
        }
    }
}

extern "C" void kernel_launch(void* const* d_in, const int* in_sizes, int n_in,
                              void* d_out, int out_size)
{
    const float* pair = (const float*)d_in[0];
    const float* Wa   = (const float*)d_in[1];
    const float* ba   = (const float*)d_in[2];
    const float* Wb   = (const float*)d_in[3];
    const float* bb   = (const float*)d_in[4];
    const float* Wg   = (const float*)d_in[5];
    const float* bg   = (const float*)d_in[6];
    const float* Wo   = (const float*)d_in[7];
    const float* bo   = (const float*)d_in[8];
    float* out = (float*)d_out;

    cudaFuncSetAttribute(proj_kernel, cudaFuncAttributeMaxDynamicSharedMemorySize, SMEM_TOTAL);
    cudaFuncSetAttribute(tri_kernel,  cudaFuncAttributeMaxDynamicSharedMemorySize, SMEM_TOTAL);
    cudaFuncSetAttribute(out_kernel,  cudaFuncAttributeMaxDynamicSharedMemorySize, SMEM_TOTAL);

    wprep_kernel <<<256,   256>>>(Wa, Wb, Wg, Wo);
    psplit_kernel<<<32768, 256>>>(pair);
    proj_kernel<<<dim3(3, 1024), THREADS, SMEM_TOTAL>>>(ba, bb, bg);
    tri_kernel <<<dim3(2, 512),  THREADS, SMEM_TOTAL>>>();
    out_kernel <<<1024,          THREADS, SMEM_TOTAL>>>(bo, out);
}

// round 6
// speedup vs baseline: 2.1882x; 1.0096x over previous
#include <cuda_runtime.h>
#include <cuda_bf16.h>
#include <cstdint>

// TriangleMultiplication, mma.sync m16n8k16 bf16, split-bf16 3-pass fp32 emu.
// R6: same as R5 except the emulation passes are swept across all (mt,nt)
// accumulators before moving to the next pass, so consecutive HMMAs never
// share an accumulator (RAW distance 1 -> 8) and the tensor pipe stays fed.

#define THREADS 512
#define STAGE   98304
#define OFF_AH  0
#define OFF_AL  16384
#define OFF_BH  32768
#define OFF_BL  65536
#define SMEM_TOTAL 196608

#define NELEM 33554432  // 2*256*256*256

static __device__ __align__(16) __nv_bfloat16 g_Ph[NELEM], g_Pl[NELEM];
static __device__ __align__(16) __nv_bfloat16 g_Ah[NELEM], g_Al[NELEM];
static __device__ __align__(16) __nv_bfloat16 g_Bh[NELEM], g_Bl[NELEM];
static __device__ __align__(16) __nv_bfloat16 g_Hh[NELEM], g_Hl[NELEM];
static __device__ __align__(16) __nv_bfloat16 g_Wh[4*65536], g_Wl[4*65536];
static __device__ float g_G[NELEM];  // sigmoid gate fp32 [m][l]

__device__ __forceinline__ uint32_t pack_bf2(__nv_bfloat16 x, __nv_bfloat16 y) {
    __nv_bfloat162 t = __halves2bfloat162(x, y);
    return *reinterpret_cast<uint32_t*>(&t);
}
__device__ __forceinline__ uint32_t smem_u32(const void* p) {
    uint32_t a;
    asm("{ .reg .u64 t; cvta.to.shared.u64 t, %1; cvt.u32.u64 %0, t; }" : "=r"(a) : "l"(p));
    return a;
}
__device__ __forceinline__ void mma16816(float d[4], const uint32_t a[4], const uint32_t b[2]) {
    asm volatile(
        "mma.sync.aligned.m16n8k16.row.col.f32.bf16.bf16.f32 "
        "{%0,%1,%2,%3}, {%4,%5,%6,%7}, {%8,%9}, {%0,%1,%2,%3};"
        : "+f"(d[0]), "+f"(d[1]), "+f"(d[2]), "+f"(d[3])
        : "r"(a[0]), "r"(a[1]), "r"(a[2]), "r"(a[3]), "r"(b[0]), "r"(b[1]));
}
__device__ __forceinline__ void ldsm_x4(uint32_t r[4], uint32_t a) {
    asm volatile("ldmatrix.sync.aligned.m8n8.x4.shared.b16 {%0,%1,%2,%3}, [%4];"
        : "=r"(r[0]), "=r"(r[1]), "=r"(r[2]), "=r"(r[3]) : "r"(a));
}
__device__ __forceinline__ void cpa(uint32_t d, const void* s) {
    asm volatile("cp.async.cg.shared.global [%0], [%1], 16;" :: "r"(d), "l"(s));
}
__device__ __forceinline__ void split2(float x, float y, uint32_t& H, uint32_t& L) {
    __nv_bfloat16 hx = __float2bfloat16_rn(x), hy = __float2bfloat16_rn(y);
    __nv_bfloat16 lx = __float2bfloat16_rn(x - __bfloat162float(hx));
    __nv_bfloat16 ly = __float2bfloat16_rn(y - __bfloat162float(hy));
    H = pack_bf2(hx, hy); L = pack_bf2(lx, ly);
}

// ROWS x 64 bf16 (128B rows, XOR-swizzled 16B chunks), src row stride 256.
template<int ROWS>
__device__ __forceinline__ void fill_plane(uint32_t dst,
                                           const __nv_bfloat16* __restrict__ src,
                                           int koff)
{
#pragma unroll
    for (int t = 0; t < ROWS*8/THREADS; ++t) {
        const int i = t*THREADS + threadIdx.x;
        const int r = i >> 3, ch = i & 7;
        const uint32_t o = (uint32_t)(r*128) + (uint32_t)((ch ^ (r & 7)) * 16);
        cpa(dst + o, src + (size_t)r*256 + koff + ch*8);
    }
}

__device__ __forceinline__ void issue_chunk(uint32_t buf,
    const __nv_bfloat16* Ah, const __nv_bfloat16* Al,
    const __nv_bfloat16* Bh, const __nv_bfloat16* Bl, int koff)
{
    fill_plane<128>(buf + OFF_AH, Ah, koff);
    fill_plane<128>(buf + OFF_AL, Al, koff);
    fill_plane<256>(buf + OFF_BH, Bh, koff);
    fill_plane<256>(buf + OFF_BL, Bl, koff);
    asm volatile("cp.async.commit_group;" ::: "memory");
}

// acc[2][8][4]: warp tile 32x64 of C = A[128,256] @ B[256,256]^T-rows.
__device__ __forceinline__ void gemm_compute(uint32_t sb,
    const __nv_bfloat16* __restrict__ Ah, const __nv_bfloat16* __restrict__ Al,
    const __nv_bfloat16* __restrict__ Bh, const __nv_bfloat16* __restrict__ Bl,
    float acc[2][8][4])
{
    const int lane = threadIdx.x & 31, wid = threadIdx.x >> 5;
    const int wm = wid >> 2, wn = wid & 3;

#pragma unroll
    for (int mt = 0; mt < 2; ++mt)
#pragma unroll
        for (int nt = 0; nt < 8; ++nt)
#pragma unroll
            for (int i = 0; i < 4; ++i) acc[mt][nt][i] = 0.f;

    issue_chunk(sb,         Ah, Al, Bh, Bl, 0);
    issue_chunk(sb + STAGE, Ah, Al, Bh, Bl, 64);

    const uint32_t xr     = lane & 7;
    const uint32_t a_base = (uint32_t)(wm*32 + (lane & 15)) * 128;
    const uint32_t a_kh   = lane >> 4;
    const uint32_t b_row  = (lane & 7) + ((lane & 16) >> 1);
    const uint32_t b_base = (uint32_t)(wn*64) * 128 + b_row * 128;
    const uint32_t b_kh   = (lane >> 3) & 1;

#pragma unroll
    for (int c = 0; c < 4; ++c) {
        if (c < 3) asm volatile("cp.async.wait_group 1;" ::: "memory");
        else       asm volatile("cp.async.wait_group 0;" ::: "memory");
        __syncthreads();
        const uint32_t buf = sb + (uint32_t)(c & 1) * STAGE;
#pragma unroll
        for (int s = 0; s < 4; ++s) {
            const uint32_t ax = (((uint32_t)s*2 + a_kh) ^ xr) * 16;
            const uint32_t bx = (((uint32_t)s*2 + b_kh) ^ xr) * 16;
            uint32_t ah[2][4], al[2][4];
#pragma unroll
            for (int mt = 0; mt < 2; ++mt) {
                const uint32_t ao = buf + a_base + (uint32_t)mt*2048 + ax;
                ldsm_x4(ah[mt], ao + OFF_AH);
                ldsm_x4(al[mt], ao + OFF_AL);
            }
#pragma unroll
            for (int half = 0; half < 2; ++half) {
                uint32_t bh[2][4], bl[2][4];
#pragma unroll
                for (int p = 0; p < 2; ++p) {
                    const uint32_t bo = buf + b_base + (uint32_t)(half*2 + p)*2048 + bx;
                    ldsm_x4(bh[p], bo + OFF_BH);
                    ldsm_x4(bl[p], bo + OFF_BL);
                }
                // Pass 1: Ah*Bh over all 8 accs (distinct -> pipelined)
#pragma unroll
                for (int mt = 0; mt < 2; ++mt)
#pragma unroll
                    for (int p = 0; p < 2; ++p)
#pragma unroll
                        for (int q = 0; q < 2; ++q)
                            mma16816(acc[mt][half*4 + p*2 + q], ah[mt], &bh[p][q*2]);
                // Pass 2: Ah*Bl
#pragma unroll
                for (int mt = 0; mt < 2; ++mt)
#pragma unroll
                    for (int p = 0; p < 2; ++p)
#pragma unroll
                        for (int q = 0; q < 2; ++q)
                            mma16816(acc[mt][half*4 + p*2 + q], ah[mt], &bl[p][q*2]);
                // Pass 3: Al*Bh
#pragma unroll
                for (int mt = 0; mt < 2; ++mt)
#pragma unroll
                    for (int p = 0; p < 2; ++p)
#pragma unroll
                        for (int q = 0; q < 2; ++q)
                            mma16816(acc[mt][half*4 + p*2 + q], al[mt], &bh[p][q*2]);
            }
        }
        __syncthreads();
        if (c < 2)
            issue_chunk(sb + (uint32_t)(c & 1) * STAGE, Ah, Al, Bh, Bl, (c + 2) * 64);
    }
}

// ---------------- prep kernels ----------------

extern "C" __global__ void psplit_kernel(const float* __restrict__ pair)
{
    const size_t i = ((size_t)blockIdx.x * 256 + threadIdx.x) * 4;
    float4 v = *(const float4*)(pair + i);
    uint32_t H0, L0, H1, L1;
    split2(v.x, v.y, H0, L0);
    split2(v.z, v.w, H1, L1);
    *(uint2*)(g_Ph + i) = make_uint2(H0, H1);
    *(uint2*)(g_Pl + i) = make_uint2(L0, L1);
}

extern "C" __global__ void wprep_kernel(const float* __restrict__ Wa,
                                        const float* __restrict__ Wb,
                                        const float* __restrict__ Wg,
                                        const float* __restrict__ Wo)
{
    const float* Ws[4] = {Wa, Wb, Wg, Wo};
    const int d = blockIdx.x, c = threadIdx.x;
#pragma unroll
    for (int w = 0; w < 4; ++w) {
        float v = Ws[w][c*256 + d];
        __nv_bfloat16 h = __float2bfloat16_rn(v);
        __nv_bfloat16 l = __float2bfloat16_rn(v - __bfloat162float(h));
        g_Wh[w*65536 + d*256 + c] = h;
        g_Wl[w*65536 + d*256 + c] = l;
    }
}

// ---------------- GEMM kernels ----------------

// grid (3, 1024): x = weight {a,b,g}, y = m-tile of 128 rows.
extern "C" __global__ void __launch_bounds__(THREADS)
proj_kernel(const float* __restrict__ ba, const float* __restrict__ bb,
            const float* __restrict__ bg)
{
    extern __shared__ char smem[];
    const uint32_t sb = smem_u32(smem);
    const int w = blockIdx.x;
    const int m0 = blockIdx.y * 128;

    float acc[2][8][4];
    gemm_compute(sb, g_Ph + (size_t)m0*256, g_Pl + (size_t)m0*256,
                 g_Wh + w*65536, g_Wl + w*65536, acc);
    __syncthreads();

    const float* bias = (w == 0) ? ba : ((w == 1) ? bb : bg);
    const int wid = threadIdx.x >> 5, lane = threadIdx.x & 31;
    const int wm = wid >> 2, wn = wid & 3;
    const int g = lane >> 2, qc = lane & 3;

    if (w == 1) {
        float* stg = (float*)smem + wid * 2080;  // 32*65
#pragma unroll
        for (int mt = 0; mt < 2; ++mt)
#pragma unroll
            for (int nt = 0; nt < 8; ++nt) {
                const int rm = mt*16 + g, cn = nt*8 + 2*qc;
                float2 bv = *(const float2*)(bias + wn*64 + cn);
                stg[rm*65 + cn]           = acc[mt][nt][0] + bv.x;
                stg[rm*65 + cn + 1]       = acc[mt][nt][1] + bv.y;
                stg[(rm + 8)*65 + cn]     = acc[mt][nt][2] + bv.x;
                stg[(rm + 8)*65 + cn + 1] = acc[mt][nt][3] + bv.y;
            }
        __syncwarp();
        const int slice = m0 >> 8;
        const int j0 = (m0 & 255) + wm * 32;
        const int m2 = 2 * (lane & 15);
        const size_t sbase = (size_t)slice * 65536;
        for (int r = lane >> 4; r < 64; r += 2) {
            float x = stg[m2*65 + r];
            float y = stg[(m2 + 1)*65 + r];
            uint32_t H, L; split2(x, y, H, L);
            const size_t idx = sbase + (size_t)(wn*64 + r)*256 + j0 + m2;
            *(uint32_t*)(g_Bh + idx) = H;
            *(uint32_t*)(g_Bl + idx) = L;
        }
    } else {
#pragma unroll
        for (int mt = 0; mt < 2; ++mt) {
            const int R0 = m0 + wm*32 + mt*16 + g;
#pragma unroll
            for (int nt = 0; nt < 8; ++nt) {
                const int col = wn*64 + nt*8 + 2*qc;
                float2 bv = *(const float2*)(bias + col);
                float v0 = acc[mt][nt][0] + bv.x, v1 = acc[mt][nt][1] + bv.y;
                float v2 = acc[mt][nt][2] + bv.x, v3 = acc[mt][nt][3] + bv.y;
                if (w == 2) {
                    v0 = 1.f/(1.f + __expf(-v0)); v1 = 1.f/(1.f + __expf(-v1));
                    v2 = 1.f/(1.f + __expf(-v2)); v3 = 1.f/(1.f + __expf(-v3));
                    *(float2*)(g_G + (size_t)R0*256 + col)       = make_float2(v0, v1);
                    *(float2*)(g_G + (size_t)(R0 + 8)*256 + col) = make_float2(v2, v3);
                } else {
                    uint32_t H, L;
                    split2(v0, v1, H, L);
                    *(uint32_t*)(g_Ah + (size_t)R0*256 + col) = H;
                    *(uint32_t*)(g_Al + (size_t)R0*256 + col) = L;
                    split2(v2, v3, H, L);
                    *(uint32_t*)(g_Ah + (size_t)(R0 + 8)*256 + col) = H;
                    *(uint32_t*)(g_Al + (size_t)(R0 + 8)*256 + col) = L;
                }
            }
        }
    }
}

// grid (2, 512): x = j-tile, y = slice. h = g * (a_s @ b_s), split-stored.
extern "C" __global__ void __launch_bounds__(THREADS)
tri_kernel()
{
    extern __shared__ char smem[];
    const uint32_t sb = smem_u32(smem);
    const int jt = blockIdx.x, slice = blockIdx.y;
    const size_t abase = (size_t)slice*65536 + (size_t)jt*128*256;
    const size_t bbase = (size_t)slice*65536;

    float acc[2][8][4];
    gemm_compute(sb, g_Ah + abase, g_Al + abase, g_Bh + bbase, g_Bl + bbase, acc);

    const int wid = threadIdx.x >> 5, lane = threadIdx.x & 31;
    const int wm = wid >> 2, wn = wid & 3;
    const int g = lane >> 2, qc = lane & 3;
    const int mbase = slice*256 + jt*128 + wm*32;

#pragma unroll
    for (int mt = 0; mt < 2; ++mt) {
        const int R0 = mbase + mt*16 + g;
#pragma unroll
        for (int nt = 0; nt < 8; ++nt) {
            const int col = wn*64 + nt*8 + 2*qc;
            float2 g0 = *(const float2*)(g_G + (size_t)R0*256 + col);
            float2 g1 = *(const float2*)(g_G + (size_t)(R0 + 8)*256 + col);
            uint32_t H, L;
            split2(acc[mt][nt][0]*g0.x, acc[mt][nt][1]*g0.y, H, L);
            *(uint32_t*)(g_Hh + (size_t)R0*256 + col) = H;
            *(uint32_t*)(g_Hl + (size_t)R0*256 + col) = L;
            split2(acc[mt][nt][2]*g1.x, acc[mt][nt][3]*g1.y, H, L);
            *(uint32_t*)(g_Hh + (size_t)(R0 + 8)*256 + col) = H;
            *(uint32_t*)(g_Hl + (size_t)(R0 + 8)*256 + col) = L;
        }
    }
}

// grid 1024: out = H @ Wo^T-rows + bo.
extern "C" __global__ void __launch_bounds__(THREADS)
out_kernel(const float* __restrict__ bo, float* __restrict__ out)
{
    extern __shared__ char smem[];
    const uint32_t sb = smem_u32(smem);
    const int m0 = blockIdx.x * 128;

    float acc[2][8][4];
    gemm_compute(sb, g_Hh + (size_t)m0*256, g_Hl + (size_t)m0*256,
                 g_Wh + 3*65536, g_Wl + 3*65536, acc);

    const int wid = threadIdx.x >> 5, lane = threadIdx.x & 31;
    const int wm = wid >> 2, wn = wid & 3;
    const int g = lane >> 2, qc = lane & 3;

#pragma unroll
    for (int mt = 0; mt < 2; ++mt) {
        const int R0 = m0 + wm*32 + mt*16 + g;
#pragma unroll
        for (int nt = 0; nt < 8; ++nt) {
            const int col = wn*64 + nt*8 + 2*qc;
            float2 bv = *(const float2*)(bo + col);
            *(float2*)(out + (size_t)R0*256 + col) =
                make_float2(acc[mt][nt][0] + bv.x, acc[mt][nt][1] + bv.y);
            *(float2*)(out + (size_t)(R0 + 8)*256 + col) =
                make_float2(acc[mt][nt][2] + bv.x, acc[mt][nt][3] + bv.y);
        }
    }
}

extern "C" void kernel_launch(void* const* d_in, const int* in_sizes, int n_in,
                              void* d_out, int out_size)
{
    const float* pair = (const float*)d_in[0];
    const float* Wa   = (const float*)d_in[1];
    const float* ba   = (const float*)d_in[2];
    const float* Wb   = (const float*)d_in[3];
    const float* bb   = (const float*)d_in[4];
    const float* Wg   = (const float*)d_in[5];
    const float* bg   = (const float*)d_in[6];
    const float* Wo   = (const float*)d_in[7];
    const float* bo   = (const float*)d_in[8];
    float* out = (float*)d_out;

    cudaFuncSetAttribute(proj_kernel, cudaFuncAttributeMaxDynamicSharedMemorySize, SMEM_TOTAL);
    cudaFuncSetAttribute(tri_kernel,  cudaFuncAttributeMaxDynamicSharedMemorySize, SMEM_TOTAL);
    cudaFuncSetAttribute(out_kernel,  cudaFuncAttributeMaxDynamicSharedMemorySize, SMEM_TOTAL);

    wprep_kernel <<<256,   256>>>(Wa, Wb, Wg, Wo);
    psplit_kernel<<<32768, 256>>>(pair);
    proj_kernel<<<dim3(3, 1024), THREADS, SMEM_TOTAL>>>(ba, bb, bg);
    tri_kernel <<<dim3(2, 512),  THREADS, SMEM_TOTAL>>>();
    out_kernel <<<1024,          THREADS, SMEM_TOTAL>>>(bo, out);
}

// round 7
// speedup vs baseline: 2.2527x; 1.0295x over previous
#include <cuda_runtime.h>
#include <cuda_bf16.h>
#include <cstdint>

// TriangleMultiplication, mma.sync m16n8k16 bf16, split-bf16 3-pass fp32 emu.
// R7: fill side switched from per-16B cp.async (LDGSTS issue-bound: 24.5k
// ops/CTA @ rt=8cyc/SMSP) to cp.async.bulk + mbarrier. Operand planes live in
// gmem as contiguous [kchunk][row][64] tile images with the XOR swizzle
// pre-applied by producers, so one bulk op moves a whole tile.

#define THREADS 512
#define STAGE   98304
#define OFF_AH  0
#define OFF_AL  16384
#define OFF_BH  32768
#define OFF_BL  65536
#define OFF_MB  196608            // two mbarriers after the 2 stages
#define SMEM_TOTAL 196640

#define NELEM 33554432            // 2*256*256*256
#define ACH 16777216UL            // A-family chunk stride bytes (131072 rows * 128B)
#define BCH 32768                 // B-family chunk stride bytes (256 rows * 128B)

// A-family planes (chunked [kc][m][64], swizzled rows): pair, a-proj, h
static __device__ __align__(16) __nv_bfloat16 g_Ph[NELEM], g_Pl[NELEM];
static __device__ __align__(16) __nv_bfloat16 g_Ah[NELEM], g_Al[NELEM];
static __device__ __align__(16) __nv_bfloat16 g_Hh[NELEM], g_Hl[NELEM];
// B-family planes: b-proj transposed per slice [s][kc][l][64]; weights [w][kc][d][64]
static __device__ __align__(16) __nv_bfloat16 g_Bh[NELEM], g_Bl[NELEM];
static __device__ __align__(16) __nv_bfloat16 g_Wh[4*65536], g_Wl[4*65536];
static __device__ float g_G[NELEM];  // sigmoid gate fp32 natural [m][l]

__device__ __forceinline__ uint32_t pack_bf2(__nv_bfloat16 x, __nv_bfloat16 y) {
    __nv_bfloat162 t = __halves2bfloat162(x, y);
    return *reinterpret_cast<uint32_t*>(&t);
}
__device__ __forceinline__ uint32_t smem_u32(const void* p) {
    uint32_t a;
    asm("{ .reg .u64 t; cvta.to.shared.u64 t, %1; cvt.u32.u64 %0, t; }" : "=r"(a) : "l"(p));
    return a;
}
__device__ __forceinline__ void mma16816(float d[4], const uint32_t a[4], const uint32_t b[2]) {
    asm volatile(
        "mma.sync.aligned.m16n8k16.row.col.f32.bf16.bf16.f32 "
        "{%0,%1,%2,%3}, {%4,%5,%6,%7}, {%8,%9}, {%0,%1,%2,%3};"
        : "+f"(d[0]), "+f"(d[1]), "+f"(d[2]), "+f"(d[3])
        : "r"(a[0]), "r"(a[1]), "r"(a[2]), "r"(a[3]), "r"(b[0]), "r"(b[1]));
}
__device__ __forceinline__ void ldsm_x4(uint32_t r[4], uint32_t a) {
    asm volatile("ldmatrix.sync.aligned.m8n8.x4.shared.b16 {%0,%1,%2,%3}, [%4];"
        : "=r"(r[0]), "=r"(r[1]), "=r"(r[2]), "=r"(r[3]) : "r"(a));
}
__device__ __forceinline__ void split2(float x, float y, uint32_t& H, uint32_t& L) {
    __nv_bfloat16 hx = __float2bfloat16_rn(x), hy = __float2bfloat16_rn(y);
    __nv_bfloat16 lx = __float2bfloat16_rn(x - __bfloat162float(hx));
    __nv_bfloat16 ly = __float2bfloat16_rn(y - __bfloat162float(hy));
    H = pack_bf2(hx, hy); L = pack_bf2(lx, ly);
}

#define MBAR_INIT(a, n) asm volatile("mbarrier.init.shared.b64 [%0], %1;" :: "r"(a), "r"(n) : "memory")
#define MBAR_EXPECT(a, b) asm volatile("mbarrier.arrive.expect_tx.shared.b64 _, [%0], %1;" :: "r"(a), "r"(b) : "memory")
#define MBAR_WAIT(a, ph) do { \
    uint32_t _m = (a), _p = (ph), _d; \
    asm volatile("{ .reg .pred p; mbarrier.try_wait.parity.acquire.cta.shared::cta.b64 p, [%1], %2; selp.b32 %0,1,0,p; }" \
        : "=r"(_d) : "r"(_m), "r"(_p) : "memory"); \
    if (!_d) { \
        asm volatile("{ .reg .pred P1; WL_%=: mbarrier.try_wait.parity.acquire.cta.shared::cta.b64 P1, [%0], %1, 0x989680; @P1 bra.uni WD_%=; bra.uni WL_%=; WD_%=: }" \
            :: "r"(_m), "r"(_p) : "memory"); \
    } } while (0)

__device__ __forceinline__ void bulk_cp(uint32_t dst, const char* src, uint32_t bytes, uint32_t mb) {
    asm volatile("cp.async.bulk.shared::cluster.global.mbarrier::complete_tx::bytes [%0], [%1], %2, [%3];"
        :: "r"(dst), "l"(src), "r"(bytes), "r"(mb) : "memory");
}

// swizzled byte offset within a chunk plane for (row, byte-in-row b)
__device__ __forceinline__ size_t swz(int row, int b) {
    return (size_t)row * 128 + (size_t)((((b >> 4) ^ (row & 7)) << 4) | (b & 15));
}

// issue one K-chunk: 96KB via 4 bulk copies. Caller = single thread.
__device__ __forceinline__ void issue_chunk(uint32_t buf, uint32_t mb,
    const char* Ah, const char* Al, const char* Bh, const char* Bl, int c)
{
    MBAR_EXPECT(mb, 98304u);
    bulk_cp(buf + OFF_AH, Ah + (size_t)c*ACH, 16384, mb);
    bulk_cp(buf + OFF_AL, Al + (size_t)c*ACH, 16384, mb);
    bulk_cp(buf + OFF_BH, Bh + c*BCH, 32768, mb);
    bulk_cp(buf + OFF_BL, Bl + c*BCH, 32768, mb);
}

// acc[2][8][4]: warp tile 32x64 of C = A[128,256] @ B[256,256]^T-rows.
// Apl/Bpl: byte pointers to hi/lo plane tile bases (chunk 0 image).
__device__ __forceinline__ void gemm_compute(uint32_t sb,
    const char* __restrict__ Ah, const char* __restrict__ Al,
    const char* __restrict__ Bh, const char* __restrict__ Bl,
    float acc[2][8][4])
{
    const int tid = threadIdx.x;
    const int lane = tid & 31, wid = tid >> 5;
    const int wm = wid >> 2, wn = wid & 3;
    const uint32_t mb0 = sb + OFF_MB, mb1 = sb + OFF_MB + 8;

#pragma unroll
    for (int mt = 0; mt < 2; ++mt)
#pragma unroll
        for (int nt = 0; nt < 8; ++nt)
#pragma unroll
            for (int i = 0; i < 4; ++i) acc[mt][nt][i] = 0.f;

    if (tid == 0) { MBAR_INIT(mb0, 1); MBAR_INIT(mb1, 1); }
    __syncthreads();
    if (tid == 0) {
        issue_chunk(sb,         mb0, Ah, Al, Bh, Bl, 0);
        issue_chunk(sb + STAGE, mb1, Ah, Al, Bh, Bl, 1);
    }

    const uint32_t xr     = lane & 7;
    const uint32_t a_base = (uint32_t)(wm*32 + (lane & 15)) * 128;
    const uint32_t a_kh   = lane >> 4;
    const uint32_t b_row  = (lane & 7) + ((lane & 16) >> 1);
    const uint32_t b_base = (uint32_t)(wn*64) * 128 + b_row * 128;
    const uint32_t b_kh   = (lane >> 3) & 1;

#pragma unroll
    for (int c = 0; c < 4; ++c) {
        MBAR_WAIT(sb + OFF_MB + (c & 1) * 8, (c >> 1) & 1);
        const uint32_t buf = sb + (uint32_t)(c & 1) * STAGE;
#pragma unroll
        for (int s = 0; s < 4; ++s) {
            const uint32_t ax = (((uint32_t)s*2 + a_kh) ^ xr) * 16;
            const uint32_t bx = (((uint32_t)s*2 + b_kh) ^ xr) * 16;
            uint32_t ah[2][4], al[2][4];
#pragma unroll
            for (int mt = 0; mt < 2; ++mt) {
                const uint32_t ao = buf + a_base + (uint32_t)mt*2048 + ax;
                ldsm_x4(ah[mt], ao + OFF_AH);
                ldsm_x4(al[mt], ao + OFF_AL);
            }
#pragma unroll
            for (int half = 0; half < 2; ++half) {
                uint32_t bh[2][4], bl[2][4];
#pragma unroll
                for (int p = 0; p < 2; ++p) {
                    const uint32_t bo = buf + b_base + (uint32_t)(half*2 + p)*2048 + bx;
                    ldsm_x4(bh[p], bo + OFF_BH);
                    ldsm_x4(bl[p], bo + OFF_BL);
                }
#pragma unroll
                for (int mt = 0; mt < 2; ++mt)
#pragma unroll
                    for (int p = 0; p < 2; ++p)
#pragma unroll
                        for (int q = 0; q < 2; ++q)
                            mma16816(acc[mt][half*4 + p*2 + q], ah[mt], &bh[p][q*2]);
#pragma unroll
                for (int mt = 0; mt < 2; ++mt)
#pragma unroll
                    for (int p = 0; p < 2; ++p)
#pragma unroll
                        for (int q = 0; q < 2; ++q)
                            mma16816(acc[mt][half*4 + p*2 + q], ah[mt], &bl[p][q*2]);
#pragma unroll
                for (int mt = 0; mt < 2; ++mt)
#pragma unroll
                    for (int p = 0; p < 2; ++p)
#pragma unroll
                        for (int q = 0; q < 2; ++q)
                            mma16816(acc[mt][half*4 + p*2 + q], al[mt], &bh[p][q*2]);
            }
        }
        __syncthreads();   // all warps done reading buf before overwrite
        if (c < 2 && tid == 0)
            issue_chunk(sb + (uint32_t)(c & 1) * STAGE, sb + OFF_MB + (c & 1) * 8,
                        Ah, Al, Bh, Bl, c + 2);
    }
}

// ---------------- prep kernels ----------------

// pair fp32 -> chunked+swizzled bf16 hi/lo planes.
extern "C" __global__ void psplit_kernel(const float* __restrict__ pair)
{
    const size_t i = ((size_t)blockIdx.x * 256 + threadIdx.x) * 4;
    const int m = (int)(i >> 8), col = (int)(i & 255);
    float4 v = *(const float4*)(pair + i);
    uint32_t H0, L0, H1, L1;
    split2(v.x, v.y, H0, L0);
    split2(v.z, v.w, H1, L1);
    const size_t off = (size_t)(col >> 6) * ACH + swz(m, (col & 63) * 2);
    *(uint2*)((char*)g_Ph + off) = make_uint2(H0, H1);
    *(uint2*)((char*)g_Pl + off) = make_uint2(L0, L1);
}

// weights -> transposed chunked+swizzled planes [w][kc][d][64].
extern "C" __global__ void wprep_kernel(const float* __restrict__ Wa,
                                        const float* __restrict__ Wb,
                                        const float* __restrict__ Wg,
                                        const float* __restrict__ Wo)
{
    const float* Ws[4] = {Wa, Wb, Wg, Wo};
    const int d = blockIdx.x, c = threadIdx.x;
    const size_t off = (size_t)(c >> 6) * BCH + swz(d, (c & 63) * 2);
#pragma unroll
    for (int w = 0; w < 4; ++w) {
        float v = Ws[w][c*256 + d];
        __nv_bfloat16 h = __float2bfloat16_rn(v);
        __nv_bfloat16 l = __float2bfloat16_rn(v - __bfloat162float(h));
        *(__nv_bfloat16*)((char*)g_Wh + (size_t)w*131072 + off) = h;
        *(__nv_bfloat16*)((char*)g_Wl + (size_t)w*131072 + off) = l;
    }
}

// ---------------- GEMM kernels ----------------

// grid (3, 1024): x = weight {a,b,g}, y = m-tile of 128 rows.
extern "C" __global__ void __launch_bounds__(THREADS)
proj_kernel(const float* __restrict__ ba, const float* __restrict__ bb,
            const float* __restrict__ bg)
{
    extern __shared__ char smem[];
    const uint32_t sb = smem_u32(smem);
    const int w = blockIdx.x;
    const int m0 = blockIdx.y * 128;

    float acc[2][8][4];
    gemm_compute(sb,
                 (const char*)g_Ph + (size_t)m0*128, (const char*)g_Pl + (size_t)m0*128,
                 (const char*)g_Wh + (size_t)w*131072, (const char*)g_Wl + (size_t)w*131072,
                 acc);
    __syncthreads();

    const float* bias = (w == 0) ? ba : ((w == 1) ? bb : bg);
    const int wid = threadIdx.x >> 5, lane = threadIdx.x & 31;
    const int wm = wid >> 2, wn = wid & 3;
    const int g = lane >> 2, qc = lane & 3;

    if (w == 1) {
        // stage warp tile [32 m][64 n] fp32 -> transposed chunked split store
        float* stg = (float*)smem + wid * 2080;  // 32*65
#pragma unroll
        for (int mt = 0; mt < 2; ++mt)
#pragma unroll
            for (int nt = 0; nt < 8; ++nt) {
                const int rm = mt*16 + g, cn = nt*8 + 2*qc;
                float2 bv = *(const float2*)(bias + wn*64 + cn);
                stg[rm*65 + cn]           = acc[mt][nt][0] + bv.x;
                stg[rm*65 + cn + 1]       = acc[mt][nt][1] + bv.y;
                stg[(rm + 8)*65 + cn]     = acc[mt][nt][2] + bv.x;
                stg[(rm + 8)*65 + cn + 1] = acc[mt][nt][3] + bv.y;
            }
        __syncwarp();
        const int slice = m0 >> 8;
        const int j0 = (m0 & 255) + wm * 32;
        const int m2 = 2 * (lane & 15);
        const int j = j0 + m2;
        const size_t coff = (size_t)slice*131072 + (size_t)(j >> 6)*BCH;
        const int jb = (j & 63) * 2;
        for (int r = lane >> 4; r < 64; r += 2) {
            float x = stg[m2*65 + r];
            float y = stg[(m2 + 1)*65 + r];
            uint32_t H, L; split2(x, y, H, L);
            const size_t off = coff + swz(wn*64 + r, jb);
            *(uint32_t*)((char*)g_Bh + off) = H;
            *(uint32_t*)((char*)g_Bl + off) = L;
        }
    } else {
#pragma unroll
        for (int mt = 0; mt < 2; ++mt) {
            const int R0 = m0 + wm*32 + mt*16 + g;
#pragma unroll
            for (int nt = 0; nt < 8; ++nt) {
                const int col = wn*64 + nt*8 + 2*qc;
                float2 bv = *(const float2*)(bias + col);
                float v0 = acc[mt][nt][0] + bv.x, v1 = acc[mt][nt][1] + bv.y;
                float v2 = acc[mt][nt][2] + bv.x, v3 = acc[mt][nt][3] + bv.y;
                if (w == 2) {
                    v0 = 1.f/(1.f + __expf(-v0)); v1 = 1.f/(1.f + __expf(-v1));
                    v2 = 1.f/(1.f + __expf(-v2)); v3 = 1.f/(1.f + __expf(-v3));
                    *(float2*)(g_G + (size_t)R0*256 + col)       = make_float2(v0, v1);
                    *(float2*)(g_G + (size_t)(R0 + 8)*256 + col) = make_float2(v2, v3);
                } else {
                    const size_t cb = (size_t)(col >> 6) * ACH;
                    const int b = (col & 63) * 2;
                    uint32_t H, L;
                    split2(v0, v1, H, L);
                    size_t off = cb + swz(R0, b);
                    *(uint32_t*)((char*)g_Ah + off) = H;
                    *(uint32_t*)((char*)g_Al + off) = L;
                    split2(v2, v3, H, L);
                    off = cb + swz(R0 + 8, b);
                    *(uint32_t*)((char*)g_Ah + off) = H;
                    *(uint32_t*)((char*)g_Al + off) = L;
                }
            }
        }
    }
}

// grid (2, 512): x = j-tile, y = slice. h = g * (a_s @ b_s), split chunked store.
extern "C" __global__ void __launch_bounds__(THREADS)
tri_kernel()
{
    extern __shared__ char smem[];
    const uint32_t sb = smem_u32(smem);
    const int jt = blockIdx.x, slice = blockIdx.y;
    const size_t arow = (size_t)(slice*256 + jt*128) * 128;   // byte offset of A tile rows

    float acc[2][8][4];
    gemm_compute(sb,
                 (const char*)g_Ah + arow, (const char*)g_Al + arow,
                 (const char*)g_Bh + (size_t)slice*131072, (const char*)g_Bl + (size_t)slice*131072,
                 acc);

    const int wid = threadIdx.x >> 5, lane = threadIdx.x & 31;
    const int wm = wid >> 2, wn = wid & 3;
    const int g = lane >> 2, qc = lane & 3;
    const int mbase = slice*256 + jt*128 + wm*32;

#pragma unroll
    for (int mt = 0; mt < 2; ++mt) {
        const int R0 = mbase + mt*16 + g;
#pragma unroll
        for (int nt = 0; nt < 8; ++nt) {
            const int col = wn*64 + nt*8 + 2*qc;
            float2 g0 = *(const float2*)(g_G + (size_t)R0*256 + col);
            float2 g1 = *(const float2*)(g_G + (size_t)(R0 + 8)*256 + col);
            const size_t cb = (size_t)(col >> 6) * ACH;
            const int b = (col & 63) * 2;
            uint32_t H, L;
            split2(acc[mt][nt][0]*g0.x, acc[mt][nt][1]*g0.y, H, L);
            size_t off = cb + swz(R0, b);
            *(uint32_t*)((char*)g_Hh + off) = H;
            *(uint32_t*)((char*)g_Hl + off) = L;
            split2(acc[mt][nt][2]*g1.x, acc[mt][nt][3]*g1.y, H, L);
            off = cb + swz(R0 + 8, b);
            *(uint32_t*)((char*)g_Hh + off) = H;
            *(uint32_t*)((char*)g_Hl + off) = L;
        }
    }
}

// grid 1024: out = H @ Wo^T-rows + bo.
extern "C" __global__ void __launch_bounds__(THREADS)
out_kernel(const float* __restrict__ bo, float* __restrict__ out)
{
    extern __shared__ char smem[];
    const uint32_t sb = smem_u32(smem);
    const int m0 = blockIdx.x * 128;

    float acc[2][8][4];
    gemm_compute(sb,
                 (const char*)g_Hh + (size_t)m0*128, (const char*)g_Hl + (size_t)m0*128,
                 (const char*)g_Wh + (size_t)3*131072, (const char*)g_Wl + (size_t)3*131072,
                 acc);

    const int wid = threadIdx.x >> 5, lane = threadIdx.x & 31;
    const int wm = wid >> 2, wn = wid & 3;
    const int g = lane >> 2, qc = lane & 3;

#pragma unroll
    for (int mt = 0; mt < 2; ++mt) {
        const int R0 = m0 + wm*32 + mt*16 + g;
#pragma unroll
        for (int nt = 0; nt < 8; ++nt) {
            const int col = wn*64 + nt*8 + 2*qc;
            float2 bv = *(const float2*)(bo + col);
            *(float2*)(out + (size_t)R0*256 + col) =
                make_float2(acc[mt][nt][0] + bv.x, acc[mt][nt][1] + bv.y);
            *(float2*)(out + (size_t)(R0 + 8)*256 + col) =
                make_float2(acc[mt][nt][2] + bv.x, acc[mt][nt][3] + bv.y);
        }
    }
}

extern "C" void kernel_launch(void* const* d_in, const int* in_sizes, int n_in,
                              void* d_out, int out_size)
{
    const float* pair = (const float*)d_in[0];
    const float* Wa   = (const float*)d_in[1];
    const float* ba   = (const float*)d_in[2];
    const float* Wb   = (const float*)d_in[3];
    const float* bb   = (const float*)d_in[4];
    const float* Wg   = (const float*)d_in[5];
    const float* bg   = (const float*)d_in[6];
    const float* Wo   = (const float*)d_in[7];
    const float* bo   = (const float*)d_in[8];
    float* out = (float*)d_out;

    cudaFuncSetAttribute(proj_kernel, cudaFuncAttributeMaxDynamicSharedMemorySize, SMEM_TOTAL);
    cudaFuncSetAttribute(tri_kernel,  cudaFuncAttributeMaxDynamicSharedMemorySize, SMEM_TOTAL);
    cudaFuncSetAttribute(out_kernel,  cudaFuncAttributeMaxDynamicSharedMemorySize, SMEM_TOTAL);

    wprep_kernel <<<256,   256>>>(Wa, Wb, Wg, Wo);
    psplit_kernel<<<32768, 256>>>(pair);
    proj_kernel<<<dim3(3, 1024), THREADS, SMEM_TOTAL>>>(ba, bb, bg);
    tri_kernel <<<dim3(2, 512),  THREADS, SMEM_TOTAL>>>();
    out_kernel <<<1024,          THREADS, SMEM_TOTAL>>>(bo, out);
}

// round 8
// speedup vs baseline: 2.6969x; 1.1972x over previous
#include <cuda_runtime.h>
#include <cuda_bf16.h>
#include <cstdint>

// TriangleMultiplication, mma.sync m16n8k16 bf16, split-bf16 3-pass fp32 emu.
// R8: 256-thread CTAs (8 warps), CTA tile 128x128, K-chunk 32, hi/lo packed
// into one 128B smem row (hi bytes 0-63, lo 64-127, XOR-swizzled 16B chunks).
// Stage 32KB, 2 stages -> ~66KB smem => 2 CTAs/SM so independent CTAs overlap
// crossbar (LDSM) bursts with tensor (HMMA) bursts.

#define THREADS 256
#define OFF_A   0
#define OFF_B   16384
#define STAGE   32768
#define OFF_MB  65536
#define SMEM_TOTAL 66624

#define NELEM 33554432            // 2*256*256*256
#define ACH 16777216UL            // A-family k-chunk stride (131072 rows * 128B)
#define BCH 32768UL               // B-family k-chunk stride (256 rows * 128B)
#define SLB 262144UL              // per-slice / per-weight B bytes (8 chunks)

// packed hi|lo images: A-family [kc8][m 131072][128B], B-family [s|w][kc8][row 256][128B]
static __device__ __align__(16) __nv_bfloat16 g_P[2*NELEM];
static __device__ __align__(16) __nv_bfloat16 g_A[2*NELEM];
static __device__ __align__(16) __nv_bfloat16 g_H[2*NELEM];
static __device__ __align__(16) __nv_bfloat16 g_B[2*NELEM];
static __device__ __align__(16) __nv_bfloat16 g_W[8*65536];
static __device__ float g_G[NELEM];   // sigmoid gate fp32 natural [m][l]

__device__ __forceinline__ uint32_t pack_bf2(__nv_bfloat16 x, __nv_bfloat16 y) {
    __nv_bfloat162 t = __halves2bfloat162(x, y);
    return *reinterpret_cast<uint32_t*>(&t);
}
__device__ __forceinline__ uint32_t smem_u32(const void* p) {
    uint32_t a;
    asm("{ .reg .u64 t; cvta.to.shared.u64 t, %1; cvt.u32.u64 %0, t; }" : "=r"(a) : "l"(p));
    return a;
}
__device__ __forceinline__ void mma16816(float d[4], const uint32_t a[4], const uint32_t b[2]) {
    asm volatile(
        "mma.sync.aligned.m16n8k16.row.col.f32.bf16.bf16.f32 "
        "{%0,%1,%2,%3}, {%4,%5,%6,%7}, {%8,%9}, {%0,%1,%2,%3};"
        : "+f"(d[0]), "+f"(d[1]), "+f"(d[2]), "+f"(d[3])
        : "r"(a[0]), "r"(a[1]), "r"(a[2]), "r"(a[3]), "r"(b[0]), "r"(b[1]));
}
__device__ __forceinline__ void ldsm_x4(uint32_t r[4], uint32_t a) {
    asm volatile("ldmatrix.sync.aligned.m8n8.x4.shared.b16 {%0,%1,%2,%3}, [%4];"
        : "=r"(r[0]), "=r"(r[1]), "=r"(r[2]), "=r"(r[3]) : "r"(a));
}
__device__ __forceinline__ void split2(float x, float y, uint32_t& H, uint32_t& L) {
    __nv_bfloat16 hx = __float2bfloat16_rn(x), hy = __float2bfloat16_rn(y);
    __nv_bfloat16 lx = __float2bfloat16_rn(x - __bfloat162float(hx));
    __nv_bfloat16 ly = __float2bfloat16_rn(y - __bfloat162float(hy));
    H = pack_bf2(hx, hy); L = pack_bf2(lx, ly);
}

#define MBAR_INIT(a, n) asm volatile("mbarrier.init.shared.b64 [%0], %1;" :: "r"(a), "r"(n) : "memory")
#define MBAR_EXPECT(a, b) asm volatile("mbarrier.arrive.expect_tx.shared.b64 _, [%0], %1;" :: "r"(a), "r"(b) : "memory")
#define MBAR_WAIT(a, ph) do { \
    uint32_t _m = (a), _p = (ph), _d; \
    asm volatile("{ .reg .pred p; mbarrier.try_wait.parity.acquire.cta.shared::cta.b64 p, [%1], %2; selp.b32 %0,1,0,p; }" \
        : "=r"(_d) : "r"(_m), "r"(_p) : "memory"); \
    if (!_d) { \
        asm volatile("{ .reg .pred P1; WL_%=: mbarrier.try_wait.parity.acquire.cta.shared::cta.b64 P1, [%0], %1, 0x989680; @P1 bra.uni WD_%=; bra.uni WL_%=; WD_%=: }" \
            :: "r"(_m), "r"(_p) : "memory"); \
    } } while (0)

__device__ __forceinline__ void bulk_cp(uint32_t dst, const char* src, uint32_t bytes, uint32_t mb) {
    asm volatile("cp.async.bulk.shared::cluster.global.mbarrier::complete_tx::bytes [%0], [%1], %2, [%3];"
        :: "r"(dst), "l"(src), "r"(bytes), "r"(mb) : "memory");
}

// swizzled in-row byte position for (row r, byte b in [0,128))
__device__ __forceinline__ uint32_t inrow(int r, int b) {
    return (uint32_t)(((((b >> 4) ^ (r & 7)) << 4)) | (b & 15));
}
// byte offsets of HI / LO bf16 for element (row, k) in a packed image
__device__ __forceinline__ size_t off_hi(int row, int k, size_t chs) {
    return (size_t)(k >> 5) * chs + (size_t)row * 128 + inrow(row, (k & 31) * 2);
}
__device__ __forceinline__ size_t off_lo(int row, int k, size_t chs) {
    return (size_t)(k >> 5) * chs + (size_t)row * 128 + inrow(row, 64 + (k & 31) * 2);
}
// store split pair (x at k, y at k+1), k even
__device__ __forceinline__ void store_split(char* base, int row, int k, float x, float y, size_t chs) {
    uint32_t H, L; split2(x, y, H, L);
    *(uint32_t*)(base + off_hi(row, k, chs)) = H;
    *(uint32_t*)(base + off_lo(row, k, chs)) = L;
}

// issue one K=32 chunk: A tile 16KB + B tile 16KB
__device__ __forceinline__ void issue_chunk(uint32_t buf, uint32_t mb,
    const char* Aimg, const char* Bimg, int c)
{
    MBAR_EXPECT(mb, 32768u);
    bulk_cp(buf + OFF_A, Aimg + (size_t)c * ACH, 16384, mb);
    bulk_cp(buf + OFF_B, Bimg + (size_t)c * BCH, 16384, mb);
}

// acc[2][8][4]: warp tile 32x64 of C = A[128,256] @ B[128,256]^T-rows.
// 8 warps: wm = wid>>1 (4 m-tiles of 32), wn = wid&1 (2 n-tiles of 64).
__device__ __forceinline__ void gemm_compute(uint32_t sb,
    const char* __restrict__ Aimg, const char* __restrict__ Bimg,
    float acc[2][8][4])
{
    const int tid = threadIdx.x;
    const int lane = tid & 31, wid = tid >> 5;
    const int wm = wid >> 1, wn = wid & 1;

#pragma unroll
    for (int mt = 0; mt < 2; ++mt)
#pragma unroll
        for (int nt = 0; nt < 8; ++nt)
#pragma unroll
            for (int i = 0; i < 4; ++i) acc[mt][nt][i] = 0.f;

    if (tid == 0) { MBAR_INIT(sb + OFF_MB, 1); MBAR_INIT(sb + OFF_MB + 8, 1); }
    __syncthreads();
    if (tid == 0) {
        issue_chunk(sb,         sb + OFF_MB,     Aimg, Bimg, 0);
        issue_chunk(sb + STAGE, sb + OFF_MB + 8, Aimg, Bimg, 1);
    }

    const uint32_t xr     = lane & 7;
    const uint32_t a_base = (uint32_t)(wm*32 + (lane & 15)) * 128;
    const uint32_t a_kh   = lane >> 4;
    const uint32_t b_row  = (lane & 7) + ((lane & 16) >> 1);
    const uint32_t b_base = (uint32_t)(wn*64) * 128 + b_row * 128;
    const uint32_t b_kh   = (lane >> 3) & 1;

#pragma unroll
    for (int c = 0; c < 8; ++c) {
        MBAR_WAIT(sb + OFF_MB + (c & 1) * 8, (c >> 1) & 1);
        const uint32_t buf = sb + (uint32_t)(c & 1) * STAGE;
#pragma unroll
        for (int s = 0; s < 2; ++s) {
            const uint32_t ach = (uint32_t)s*2 + a_kh;   // hi chunks 0..3
            const uint32_t bch = (uint32_t)s*2 + b_kh;
            const uint32_t ax_h = ((ach ^ xr) << 4),       ax_l = (((ach + 4) ^ xr) << 4);
            const uint32_t bx_h = ((bch ^ xr) << 4),       bx_l = (((bch + 4) ^ xr) << 4);
            uint32_t ah[2][4], al[2][4];
#pragma unroll
            for (int mt = 0; mt < 2; ++mt) {
                const uint32_t ao = buf + OFF_A + a_base + (uint32_t)mt*2048;
                ldsm_x4(ah[mt], ao + ax_h);
                ldsm_x4(al[mt], ao + ax_l);
            }
#pragma unroll
            for (int half = 0; half < 2; ++half) {
                uint32_t bh[2][4], bl[2][4];
#pragma unroll
                for (int p = 0; p < 2; ++p) {
                    const uint32_t bo = buf + OFF_B + b_base + (uint32_t)(half*2 + p)*2048;
                    ldsm_x4(bh[p], bo + bx_h);
                    ldsm_x4(bl[p], bo + bx_l);
                }
#pragma unroll
                for (int mt = 0; mt < 2; ++mt)
#pragma unroll
                    for (int p = 0; p < 2; ++p)
#pragma unroll
                        for (int q = 0; q < 2; ++q)
                            mma16816(acc[mt][half*4 + p*2 + q], ah[mt], &bh[p][q*2]);
#pragma unroll
                for (int mt = 0; mt < 2; ++mt)
#pragma unroll
                    for (int p = 0; p < 2; ++p)
#pragma unroll
                        for (int q = 0; q < 2; ++q)
                            mma16816(acc[mt][half*4 + p*2 + q], ah[mt], &bl[p][q*2]);
#pragma unroll
                for (int mt = 0; mt < 2; ++mt)
#pragma unroll
                    for (int p = 0; p < 2; ++p)
#pragma unroll
                        for (int q = 0; q < 2; ++q)
                            mma16816(acc[mt][half*4 + p*2 + q], al[mt], &bh[p][q*2]);
            }
        }
        __syncthreads();
        if (c < 6 && tid == 0)
            issue_chunk(sb + (uint32_t)(c & 1) * STAGE, sb + OFF_MB + (c & 1) * 8,
                        Aimg, Bimg, c + 2);
    }
}

// ---------------- prep kernels ----------------

extern "C" __global__ void psplit_kernel(const float* __restrict__ pair)
{
    const size_t i = ((size_t)blockIdx.x * 256 + threadIdx.x) * 4;
    const int m = (int)(i >> 8), col = (int)(i & 255);
    float4 v = *(const float4*)(pair + i);
    uint32_t H0, L0, H1, L1;
    split2(v.x, v.y, H0, L0);
    split2(v.z, v.w, H1, L1);
    char* base = (char*)g_P;
    const size_t oh = off_hi(m, col, ACH);   // 8-aligned within 16B chunk
    const size_t ol = off_lo(m, col, ACH);
    *(uint2*)(base + oh) = make_uint2(H0, H1);
    *(uint2*)(base + ol) = make_uint2(L0, L1);
}

extern "C" __global__ void wprep_kernel(const float* __restrict__ Wa,
                                        const float* __restrict__ Wb,
                                        const float* __restrict__ Wg,
                                        const float* __restrict__ Wo)
{
    const float* Ws[4] = {Wa, Wb, Wg, Wo};
    const int d = blockIdx.x, c = threadIdx.x;
#pragma unroll
    for (int w = 0; w < 4; ++w) {
        float v = Ws[w][c*256 + d];
        __nv_bfloat16 h = __float2bfloat16_rn(v);
        __nv_bfloat16 l = __float2bfloat16_rn(v - __bfloat162float(h));
        char* base = (char*)g_W + (size_t)w * SLB;
        *(__nv_bfloat16*)(base + off_hi(d, c, BCH)) = h;
        *(__nv_bfloat16*)(base + off_lo(d, c, BCH)) = l;
    }
}

// ---------------- GEMM kernels ----------------

// grid (6, 1024): x = w*2 + nt, y = m-tile of 128.
extern "C" __global__ void __launch_bounds__(THREADS, 2)
proj_kernel(const float* __restrict__ ba, const float* __restrict__ bb,
            const float* __restrict__ bg)
{
    extern __shared__ char smem[];
    const uint32_t sb = smem_u32(smem);
    const int w = blockIdx.x >> 1, nt = blockIdx.x & 1;
    const int m0 = blockIdx.y * 128;

    float acc[2][8][4];
    gemm_compute(sb,
                 (const char*)g_P + (size_t)m0*128,
                 (const char*)g_W + (size_t)w*SLB + (size_t)nt*16384,
                 acc);
    __syncthreads();

    const float* bias = (w == 0) ? ba : ((w == 1) ? bb : bg);
    const int wid = threadIdx.x >> 5, lane = threadIdx.x & 31;
    const int wm = wid >> 1, wn = wid & 1;
    const int g = lane >> 2, qc = lane & 3;

    if (w == 1) {
        // stage warp tile [32 m][64 n] fp32 -> transposed packed store to g_B
        float* stg = (float*)smem + wid * 2080;  // 32*65
#pragma unroll
        for (int mt = 0; mt < 2; ++mt)
#pragma unroll
            for (int ntl = 0; ntl < 8; ++ntl) {
                const int rm = mt*16 + g, cn = ntl*8 + 2*qc;
                float2 bv = *(const float2*)(bias + nt*128 + wn*64 + cn);
                stg[rm*65 + cn]           = acc[mt][ntl][0] + bv.x;
                stg[rm*65 + cn + 1]       = acc[mt][ntl][1] + bv.y;
                stg[(rm + 8)*65 + cn]     = acc[mt][ntl][2] + bv.x;
                stg[(rm + 8)*65 + cn + 1] = acc[mt][ntl][3] + bv.y;
            }
        __syncwarp();
        const int slice = m0 >> 8;
        const int j0 = (m0 & 255) + wm * 32;
        const int m2 = 2 * (lane & 15);
        const int j = j0 + m2;                 // k index (even)
        char* base = (char*)g_B + (size_t)slice * SLB;
        for (int r = lane >> 4; r < 64; r += 2) {
            const int l = nt*128 + wn*64 + r;  // row in B image
            store_split(base, l, j, stg[m2*65 + r], stg[(m2 + 1)*65 + r], BCH);
        }
    } else {
#pragma unroll
        for (int mt = 0; mt < 2; ++mt) {
            const int R0 = m0 + wm*32 + mt*16 + g;
#pragma unroll
            for (int ntl = 0; ntl < 8; ++ntl) {
                const int col = nt*128 + wn*64 + ntl*8 + 2*qc;
                float2 bv = *(const float2*)(bias + col);
                float v0 = acc[mt][ntl][0] + bv.x, v1 = acc[mt][ntl][1] + bv.y;
                float v2 = acc[mt][ntl][2] + bv.x, v3 = acc[mt][ntl][3] + bv.y;
                if (w == 2) {
                    v0 = 1.f/(1.f + __expf(-v0)); v1 = 1.f/(1.f + __expf(-v1));
                    v2 = 1.f/(1.f + __expf(-v2)); v3 = 1.f/(1.f + __expf(-v3));
                    *(float2*)(g_G + (size_t)R0*256 + col)       = make_float2(v0, v1);
                    *(float2*)(g_G + (size_t)(R0 + 8)*256 + col) = make_float2(v2, v3);
                } else {
                    store_split((char*)g_A, R0,     col, v0, v1, ACH);
                    store_split((char*)g_A, R0 + 8, col, v2, v3, ACH);
                }
            }
        }
    }
}

// grid (4, 512): x = jt + 2*lt, y = slice. h = g * (a_s @ b_s).
extern "C" __global__ void __launch_bounds__(THREADS, 2)
tri_kernel()
{
    extern __shared__ char smem[];
    const uint32_t sb = smem_u32(smem);
    const int jt = blockIdx.x & 1, lt = blockIdx.x >> 1;
    const int slice = blockIdx.y;

    float acc[2][8][4];
    gemm_compute(sb,
                 (const char*)g_A + (size_t)(slice*256 + jt*128)*128,
                 (const char*)g_B + (size_t)slice*SLB + (size_t)lt*16384,
                 acc);

    const int wid = threadIdx.x >> 5, lane = threadIdx.x & 31;
    const int wm = wid >> 1, wn = wid & 1;
    const int g = lane >> 2, qc = lane & 3;
    const int mbase = slice*256 + jt*128 + wm*32;

#pragma unroll
    for (int mt = 0; mt < 2; ++mt) {
        const int R0 = mbase + mt*16 + g;
#pragma unroll
        for (int ntl = 0; ntl < 8; ++ntl) {
            const int col = lt*128 + wn*64 + ntl*8 + 2*qc;
            float2 g0 = *(const float2*)(g_G + (size_t)R0*256 + col);
            float2 g1 = *(const float2*)(g_G + (size_t)(R0 + 8)*256 + col);
            store_split((char*)g_H, R0,     col, acc[mt][ntl][0]*g0.x, acc[mt][ntl][1]*g0.y, ACH);
            store_split((char*)g_H, R0 + 8, col, acc[mt][ntl][2]*g1.x, acc[mt][ntl][3]*g1.y, ACH);
        }
    }
}

// grid (2, 1024): x = nt, y = m-tile. out = H @ Wo^T-rows + bo.
extern "C" __global__ void __launch_bounds__(THREADS, 2)
out_kernel(const float* __restrict__ bo, float* __restrict__ out)
{
    extern __shared__ char smem[];
    const uint32_t sb = smem_u32(smem);
    const int nt = blockIdx.x;
    const int m0 = blockIdx.y * 128;

    float acc[2][8][4];
    gemm_compute(sb,
                 (const char*)g_H + (size_t)m0*128,
                 (const char*)g_W + (size_t)3*SLB + (size_t)nt*16384,
                 acc);

    const int wid = threadIdx.x >> 5, lane = threadIdx.x & 31;
    const int wm = wid >> 1, wn = wid & 1;
    const int g = lane >> 2, qc = lane & 3;

#pragma unroll
    for (int mt = 0; mt < 2; ++mt) {
        const int R0 = m0 + wm*32 + mt*16 + g;
#pragma unroll
        for (int ntl = 0; ntl < 8; ++ntl) {
            const int col = nt*128 + wn*64 + ntl*8 + 2*qc;
            float2 bv = *(const float2*)(bo + col);
            *(float2*)(out + (size_t)R0*256 + col) =
                make_float2(acc[mt][ntl][0] + bv.x, acc[mt][ntl][1] + bv.y);
            *(float2*)(out + (size_t)(R0 + 8)*256 + col) =
                make_float2(acc[mt][ntl][2] + bv.x, acc[mt][ntl][3] + bv.y);
        }
    }
}

extern "C" void kernel_launch(void* const* d_in, const int* in_sizes, int n_in,
                              void* d_out, int out_size)
{
    const float* pair = (const float*)d_in[0];
    const float* Wa   = (const float*)d_in[1];
    const float* ba   = (const float*)d_in[2];
    const float* Wb   = (const float*)d_in[3];
    const float* bb   = (const float*)d_in[4];
    const float* Wg   = (const float*)d_in[5];
    const float* bg   = (const float*)d_in[6];
    const float* Wo   = (const float*)d_in[7];
    const float* bo   = (const float*)d_in[8];
    float* out = (float*)d_out;

    cudaFuncSetAttribute(proj_kernel, cudaFuncAttributeMaxDynamicSharedMemorySize, SMEM_TOTAL);
    cudaFuncSetAttribute(tri_kernel,  cudaFuncAttributeMaxDynamicSharedMemorySize, SMEM_TOTAL);
    cudaFuncSetAttribute(out_kernel,  cudaFuncAttributeMaxDynamicSharedMemorySize, SMEM_TOTAL);

    wprep_kernel <<<256,   256>>>(Wa, Wb, Wg, Wo);
    psplit_kernel<<<32768, 256>>>(pair);
    proj_kernel<<<dim3(6, 1024), THREADS, SMEM_TOTAL>>>(ba, bb, bg);
    tri_kernel <<<dim3(4, 512),  THREADS, SMEM_TOTAL>>>();
    out_kernel <<<dim3(2, 1024), THREADS, SMEM_TOTAL>>>(bo, out);
}

// round 9
// speedup vs baseline: 2.7028x; 1.0022x over previous
#include <cuda_runtime.h>
#include <cuda_bf16.h>
#include <cstdint>

// TriangleMultiplication, mma.sync m16n8k16 bf16, split-bf16 3-pass fp32 emu.
// R9: 3-stage cp.async.bulk pipeline (was 2) to keep 2 chunks in flight and
// hide DRAM latency at chunk boundaries. 256-thread CTAs, tile 128x128,
// K-chunk 32, hi/lo packed per 128B swizzled smem row, 2 CTAs/SM.

#define THREADS 256
#define OFF_A   0
#define OFF_B   16384
#define STAGE   32768
#define NSTAGE  3
#define OFF_MB  (STAGE*NSTAGE)
#define SMEM_TOTAL (STAGE*NSTAGE + 32)

#define NELEM 33554432            // 2*256*256*256
#define ACH 16777216UL            // A-family k-chunk stride (131072 rows * 128B)
#define BCH 32768UL               // B-family k-chunk stride (256 rows * 128B)
#define SLB 262144UL              // per-slice / per-weight B bytes (8 chunks)

// packed hi|lo images: A-family [kc8][m 131072][128B], B-family [s|w][kc8][row 256][128B]
static __device__ __align__(16) __nv_bfloat16 g_P[2*NELEM];
static __device__ __align__(16) __nv_bfloat16 g_A[2*NELEM];
static __device__ __align__(16) __nv_bfloat16 g_H[2*NELEM];
static __device__ __align__(16) __nv_bfloat16 g_B[2*NELEM];
static __device__ __align__(16) __nv_bfloat16 g_W[8*65536];
static __device__ float g_G[NELEM];   // sigmoid gate fp32 natural [m][l]

__device__ __forceinline__ uint32_t pack_bf2(__nv_bfloat16 x, __nv_bfloat16 y) {
    __nv_bfloat162 t = __halves2bfloat162(x, y);
    return *reinterpret_cast<uint32_t*>(&t);
}
__device__ __forceinline__ uint32_t smem_u32(const void* p) {
    uint32_t a;
    asm("{ .reg .u64 t; cvta.to.shared.u64 t, %1; cvt.u32.u64 %0, t; }" : "=r"(a) : "l"(p));
    return a;
}
__device__ __forceinline__ void mma16816(float d[4], const uint32_t a[4], const uint32_t b[2]) {
    asm volatile(
        "mma.sync.aligned.m16n8k16.row.col.f32.bf16.bf16.f32 "
        "{%0,%1,%2,%3}, {%4,%5,%6,%7}, {%8,%9}, {%0,%1,%2,%3};"
        : "+f"(d[0]), "+f"(d[1]), "+f"(d[2]), "+f"(d[3])
        : "r"(a[0]), "r"(a[1]), "r"(a[2]), "r"(a[3]), "r"(b[0]), "r"(b[1]));
}
__device__ __forceinline__ void ldsm_x4(uint32_t r[4], uint32_t a) {
    asm volatile("ldmatrix.sync.aligned.m8n8.x4.shared.b16 {%0,%1,%2,%3}, [%4];"
        : "=r"(r[0]), "=r"(r[1]), "=r"(r[2]), "=r"(r[3]) : "r"(a));
}
__device__ __forceinline__ void split2(float x, float y, uint32_t& H, uint32_t& L) {
    __nv_bfloat16 hx = __float2bfloat16_rn(x), hy = __float2bfloat16_rn(y);
    __nv_bfloat16 lx = __float2bfloat16_rn(x - __bfloat162float(hx));
    __nv_bfloat16 ly = __float2bfloat16_rn(y - __bfloat162float(hy));
    H = pack_bf2(hx, hy); L = pack_bf2(lx, ly);
}

#define MBAR_INIT(a, n) asm volatile("mbarrier.init.shared.b64 [%0], %1;" :: "r"(a), "r"(n) : "memory")
#define MBAR_EXPECT(a, b) asm volatile("mbarrier.arrive.expect_tx.shared.b64 _, [%0], %1;" :: "r"(a), "r"(b) : "memory")
#define MBAR_WAIT(a, ph) do { \
    uint32_t _m = (a), _p = (ph), _d; \
    asm volatile("{ .reg .pred p; mbarrier.try_wait.parity.acquire.cta.shared::cta.b64 p, [%1], %2; selp.b32 %0,1,0,p; }" \
        : "=r"(_d) : "r"(_m), "r"(_p) : "memory"); \
    if (!_d) { \
        asm volatile("{ .reg .pred P1; WL_%=: mbarrier.try_wait.parity.acquire.cta.shared::cta.b64 P1, [%0], %1, 0x989680; @P1 bra.uni WD_%=; bra.uni WL_%=; WD_%=: }" \
            :: "r"(_m), "r"(_p) : "memory"); \
    } } while (0)

__device__ __forceinline__ void bulk_cp(uint32_t dst, const char* src, uint32_t bytes, uint32_t mb) {
    asm volatile("cp.async.bulk.shared::cluster.global.mbarrier::complete_tx::bytes [%0], [%1], %2, [%3];"
        :: "r"(dst), "l"(src), "r"(bytes), "r"(mb) : "memory");
}

// swizzled in-row byte position for (row r, byte b in [0,128))
__device__ __forceinline__ uint32_t inrow(int r, int b) {
    return (uint32_t)(((((b >> 4) ^ (r & 7)) << 4)) | (b & 15));
}
__device__ __forceinline__ size_t off_hi(int row, int k, size_t chs) {
    return (size_t)(k >> 5) * chs + (size_t)row * 128 + inrow(row, (k & 31) * 2);
}
__device__ __forceinline__ size_t off_lo(int row, int k, size_t chs) {
    return (size_t)(k >> 5) * chs + (size_t)row * 128 + inrow(row, 64 + (k & 31) * 2);
}
__device__ __forceinline__ void store_split(char* base, int row, int k, float x, float y, size_t chs) {
    uint32_t H, L; split2(x, y, H, L);
    *(uint32_t*)(base + off_hi(row, k, chs)) = H;
    *(uint32_t*)(base + off_lo(row, k, chs)) = L;
}

// issue one K=32 chunk: A tile 16KB + B tile 16KB into stage st
__device__ __forceinline__ void issue_chunk(uint32_t sb, int st,
    const char* Aimg, const char* Bimg, int c)
{
    const uint32_t buf = sb + (uint32_t)st * STAGE;
    const uint32_t mb  = sb + OFF_MB + (uint32_t)st * 8;
    MBAR_EXPECT(mb, 32768u);
    bulk_cp(buf + OFF_A, Aimg + (size_t)c * ACH, 16384, mb);
    bulk_cp(buf + OFF_B, Bimg + (size_t)c * BCH, 16384, mb);
}

// acc[2][8][4]: warp tile 32x64 of C = A[128,256] @ B[128,256]^T-rows.
__device__ __forceinline__ void gemm_compute(uint32_t sb,
    const char* __restrict__ Aimg, const char* __restrict__ Bimg,
    float acc[2][8][4])
{
    const int tid = threadIdx.x;
    const int lane = tid & 31, wid = tid >> 5;
    const int wm = wid >> 1, wn = wid & 1;

#pragma unroll
    for (int mt = 0; mt < 2; ++mt)
#pragma unroll
        for (int nt = 0; nt < 8; ++nt)
#pragma unroll
            for (int i = 0; i < 4; ++i) acc[mt][nt][i] = 0.f;

    if (tid == 0) {
        MBAR_INIT(sb + OFF_MB,      1);
        MBAR_INIT(sb + OFF_MB + 8,  1);
        MBAR_INIT(sb + OFF_MB + 16, 1);
    }
    __syncthreads();
    if (tid == 0) {
        issue_chunk(sb, 0, Aimg, Bimg, 0);
        issue_chunk(sb, 1, Aimg, Bimg, 1);
        issue_chunk(sb, 2, Aimg, Bimg, 2);
    }

    const uint32_t xr     = lane & 7;
    const uint32_t a_base = (uint32_t)(wm*32 + (lane & 15)) * 128;
    const uint32_t a_kh   = lane >> 4;
    const uint32_t b_row  = (lane & 7) + ((lane & 16) >> 1);
    const uint32_t b_base = (uint32_t)(wn*64) * 128 + b_row * 128;
    const uint32_t b_kh   = (lane >> 3) & 1;

#pragma unroll
    for (int c = 0; c < 8; ++c) {
        const int st = c % NSTAGE;
        MBAR_WAIT(sb + OFF_MB + st * 8, (c / NSTAGE) & 1);
        const uint32_t buf = sb + (uint32_t)st * STAGE;
#pragma unroll
        for (int s = 0; s < 2; ++s) {
            const uint32_t ach = (uint32_t)s*2 + a_kh;
            const uint32_t bch = (uint32_t)s*2 + b_kh;
            const uint32_t ax_h = ((ach ^ xr) << 4), ax_l = (((ach + 4) ^ xr) << 4);
            const uint32_t bx_h = ((bch ^ xr) << 4), bx_l = (((bch + 4) ^ xr) << 4);
            uint32_t ah[2][4], al[2][4];
#pragma unroll
            for (int mt = 0; mt < 2; ++mt) {
                const uint32_t ao = buf + OFF_A + a_base + (uint32_t)mt*2048;
                ldsm_x4(ah[mt], ao + ax_h);
                ldsm_x4(al[mt], ao + ax_l);
            }
#pragma unroll
            for (int half = 0; half < 2; ++half) {
                uint32_t bh[2][4], bl[2][4];
#pragma unroll
                for (int p = 0; p < 2; ++p) {
                    const uint32_t bo = buf + OFF_B + b_base + (uint32_t)(half*2 + p)*2048;
                    ldsm_x4(bh[p], bo + bx_h);
                    ldsm_x4(bl[p], bo + bx_l);
                }
#pragma unroll
                for (int mt = 0; mt < 2; ++mt)
#pragma unroll
                    for (int p = 0; p < 2; ++p)
#pragma unroll
                        for (int q = 0; q < 2; ++q)
                            mma16816(acc[mt][half*4 + p*2 + q], ah[mt], &bh[p][q*2]);
#pragma unroll
                for (int mt = 0; mt < 2; ++mt)
#pragma unroll
                    for (int p = 0; p < 2; ++p)
#pragma unroll
                        for (int q = 0; q < 2; ++q)
                            mma16816(acc[mt][half*4 + p*2 + q], ah[mt], &bl[p][q*2]);
#pragma unroll
                for (int mt = 0; mt < 2; ++mt)
#pragma unroll
                    for (int p = 0; p < 2; ++p)
#pragma unroll
                        for (int q = 0; q < 2; ++q)
                            mma16816(acc[mt][half*4 + p*2 + q], al[mt], &bh[p][q*2]);
            }
        }
        __syncthreads();
        if (c < 5 && tid == 0)
            issue_chunk(sb, st, Aimg, Bimg, c + NSTAGE);
    }
}

// ---------------- prep kernels ----------------

extern "C" __global__ void psplit_kernel(const float* __restrict__ pair)
{
    const size_t i = ((size_t)blockIdx.x * 256 + threadIdx.x) * 4;
    const int m = (int)(i >> 8), col = (int)(i & 255);
    float4 v = *(const float4*)(pair + i);
    uint32_t H0, L0, H1, L1;
    split2(v.x, v.y, H0, L0);
    split2(v.z, v.w, H1, L1);
    char* base = (char*)g_P;
    *(uint2*)(base + off_hi(m, col, ACH)) = make_uint2(H0, H1);
    *(uint2*)(base + off_lo(m, col, ACH)) = make_uint2(L0, L1);
}

extern "C" __global__ void wprep_kernel(const float* __restrict__ Wa,
                                        const float* __restrict__ Wb,
                                        const float* __restrict__ Wg,
                                        const float* __restrict__ Wo)
{
    const float* Ws[4] = {Wa, Wb, Wg, Wo};
    const int d = blockIdx.x, c = threadIdx.x;
#pragma unroll
    for (int w = 0; w < 4; ++w) {
        float v = Ws[w][c*256 + d];
        __nv_bfloat16 h = __float2bfloat16_rn(v);
        __nv_bfloat16 l = __float2bfloat16_rn(v - __bfloat162float(h));
        char* base = (char*)g_W + (size_t)w * SLB;
        *(__nv_bfloat16*)(base + off_hi(d, c, BCH)) = h;
        *(__nv_bfloat16*)(base + off_lo(d, c, BCH)) = l;
    }
}

// ---------------- GEMM kernels ----------------

// grid (6, 1024): x = w*2 + nt, y = m-tile of 128.
extern "C" __global__ void __launch_bounds__(THREADS, 2)
proj_kernel(const float* __restrict__ ba, const float* __restrict__ bb,
            const float* __restrict__ bg)
{
    extern __shared__ char smem[];
    const uint32_t sb = smem_u32(smem);
    const int w = blockIdx.x >> 1, nt = blockIdx.x & 1;
    const int m0 = blockIdx.y * 128;

    float acc[2][8][4];
    gemm_compute(sb,
                 (const char*)g_P + (size_t)m0*128,
                 (const char*)g_W + (size_t)w*SLB + (size_t)nt*16384,
                 acc);
    __syncthreads();

    const float* bias = (w == 0) ? ba : ((w == 1) ? bb : bg);
    const int wid = threadIdx.x >> 5, lane = threadIdx.x & 31;
    const int wm = wid >> 1, wn = wid & 1;
    const int g = lane >> 2, qc = lane & 3;

    if (w == 1) {
        float* stg = (float*)smem + wid * 2080;  // 32*65
#pragma unroll
        for (int mt = 0; mt < 2; ++mt)
#pragma unroll
            for (int ntl = 0; ntl < 8; ++ntl) {
                const int rm = mt*16 + g, cn = ntl*8 + 2*qc;
                float2 bv = *(const float2*)(bias + nt*128 + wn*64 + cn);
                stg[rm*65 + cn]           = acc[mt][ntl][0] + bv.x;
                stg[rm*65 + cn + 1]       = acc[mt][ntl][1] + bv.y;
                stg[(rm + 8)*65 + cn]     = acc[mt][ntl][2] + bv.x;
                stg[(rm + 8)*65 + cn + 1] = acc[mt][ntl][3] + bv.y;
            }
        __syncwarp();
        const int slice = m0 >> 8;
        const int j0 = (m0 & 255) + wm * 32;
        const int m2 = 2 * (lane & 15);
        const int j = j0 + m2;
        char* base = (char*)g_B + (size_t)slice * SLB;
        for (int r = lane >> 4; r < 64; r += 2) {
            const int l = nt*128 + wn*64 + r;
            store_split(base, l, j, stg[m2*65 + r], stg[(m2 + 1)*65 + r], BCH);
        }
    } else {
#pragma unroll
        for (int mt = 0; mt < 2; ++mt) {
            const int R0 = m0 + wm*32 + mt*16 + g;
#pragma unroll
            for (int ntl = 0; ntl < 8; ++ntl) {
                const int col = nt*128 + wn*64 + ntl*8 + 2*qc;
                float2 bv = *(const float2*)(bias + col);
                float v0 = acc[mt][ntl][0] + bv.x, v1 = acc[mt][ntl][1] + bv.y;
                float v2 = acc[mt][ntl][2] + bv.x, v3 = acc[mt][ntl][3] + bv.y;
                if (w == 2) {
                    v0 = 1.f/(1.f + __expf(-v0)); v1 = 1.f/(1.f + __expf(-v1));
                    v2 = 1.f/(1.f + __expf(-v2)); v3 = 1.f/(1.f + __expf(-v3));
                    *(float2*)(g_G + (size_t)R0*256 + col)       = make_float2(v0, v1);
                    *(float2*)(g_G + (size_t)(R0 + 8)*256 + col) = make_float2(v2, v3);
                } else {
                    store_split((char*)g_A, R0,     col, v0, v1, ACH);
                    store_split((char*)g_A, R0 + 8, col, v2, v3, ACH);
                }
            }
        }
    }
}

// grid (4, 512): x = jt + 2*lt, y = slice. h = g * (a_s @ b_s).
extern "C" __global__ void __launch_bounds__(THREADS, 2)
tri_kernel()
{
    extern __shared__ char smem[];
    const uint32_t sb = smem_u32(smem);
    const int jt = blockIdx.x & 1, lt = blockIdx.x >> 1;
    const int slice = blockIdx.y;

    float acc[2][8][4];
    gemm_compute(sb,
                 (const char*)g_A + (size_t)(slice*256 + jt*128)*128,
                 (const char*)g_B + (size_t)slice*SLB + (size_t)lt*16384,
                 acc);

    const int wid = threadIdx.x >> 5, lane = threadIdx.x & 31;
    const int wm = wid >> 1, wn = wid & 1;
    const int g = lane >> 2, qc = lane & 3;
    const int mbase = slice*256 + jt*128 + wm*32;

#pragma unroll
    for (int mt = 0; mt < 2; ++mt) {
        const int R0 = mbase + mt*16 + g;
#pragma unroll
        for (int ntl = 0; ntl < 8; ++ntl) {
            const int col = lt*128 + wn*64 + ntl*8 + 2*qc;
            float2 g0 = *(const float2*)(g_G + (size_t)R0*256 + col);
            float2 g1 = *(const float2*)(g_G + (size_t)(R0 + 8)*256 + col);
            store_split((char*)g_H, R0,     col, acc[mt][ntl][0]*g0.x, acc[mt][ntl][1]*g0.y, ACH);
            store_split((char*)g_H, R0 + 8, col, acc[mt][ntl][2]*g1.x, acc[mt][ntl][3]*g1.y, ACH);
        }
    }
}

// grid (2, 1024): x = nt, y = m-tile. out = H @ Wo^T-rows + bo.
extern "C" __global__ void __launch_bounds__(THREADS, 2)
out_kernel(const float* __restrict__ bo, float* __restrict__ out)
{
    extern __shared__ char smem[];
    const uint32_t sb = smem_u32(smem);
    const int nt = blockIdx.x;
    const int m0 = blockIdx.y * 128;

    float acc[2][8][4];
    gemm_compute(sb,
                 (const char*)g_H + (size_t)m0*128,
                 (const char*)g_W + (size_t)3*SLB + (size_t)nt*16384,
                 acc);

    const int wid = threadIdx.x >> 5, lane = threadIdx.x & 31;
    const int wm = wid >> 1, wn = wid & 1;
    const int g = lane >> 2, qc = lane & 3;

#pragma unroll
    for (int mt = 0; mt < 2; ++mt) {
        const int R0 = m0 + wm*32 + mt*16 + g;
#pragma unroll
        for (int ntl = 0; ntl < 8; ++ntl) {
            const int col = nt*128 + wn*64 + ntl*8 + 2*qc;
            float2 bv = *(const float2*)(bo + col);
            *(float2*)(out + (size_t)R0*256 + col) =
                make_float2(acc[mt][ntl][0] + bv.x, acc[mt][ntl][1] + bv.y);
            *(float2*)(out + (size_t)(R0 + 8)*256 + col) =
                make_float2(acc[mt][ntl][2] + bv.x, acc[mt][ntl][3] + bv.y);
        }
    }
}

extern "C" void kernel_launch(void* const* d_in, const int* in_sizes, int n_in,
                              void* d_out, int out_size)
{
    const float* pair = (const float*)d_in[0];
    const float* Wa   = (const float*)d_in[1];
    const float* ba   = (const float*)d_in[2];
    const float* Wb   = (const float*)d_in[3];
    const float* bb   = (const float*)d_in[4];
    const float* Wg   = (const float*)d_in[5];
    const float* bg   = (const float*)d_in[6];
    const float* Wo   = (const float*)d_in[7];
    const float* bo   = (const float*)d_in[8];
    float* out = (float*)d_out;

    cudaFuncSetAttribute(proj_kernel, cudaFuncAttributeMaxDynamicSharedMemorySize, SMEM_TOTAL);
    cudaFuncSetAttribute(tri_kernel,  cudaFuncAttributeMaxDynamicSharedMemorySize, SMEM_TOTAL);
    cudaFuncSetAttribute(out_kernel,  cudaFuncAttributeMaxDynamicSharedMemorySize, SMEM_TOTAL);

    wprep_kernel <<<256,   256>>>(Wa, Wb, Wg, Wo);
    psplit_kernel<<<32768, 256>>>(pair);
    proj_kernel<<<dim3(6, 1024), THREADS, SMEM_TOTAL>>>(ba, bb, bg);
    tri_kernel <<<dim3(4, 512),  THREADS, SMEM_TOTAL>>>();
    out_kernel <<<dim3(2, 1024), THREADS, SMEM_TOTAL>>>(bo, out);
}

// round 10
// speedup vs baseline: 2.7250x; 1.0082x over previous
#include <cuda_runtime.h>
#include <cuda_bf16.h>
#include <cstdint>

// TriangleMultiplication, mma.sync m16n8k16 bf16, split-bf16 3-pass fp32 emu.
// R10: intra-mainloop __syncthreads removed. Per-stage producer/consumer
// mbarriers: full[st] (tx from cp.async.bulk) + empty[st] (count=8, elected
// arrive per warp after consumption). Warps free-run with skew so LDSM and
// HMMA phases of different warps overlap inside a CTA.

#define THREADS 256
#define OFF_A   0
#define OFF_B   16384
#define STAGE   32768
#define NSTAGE  3
#define OFF_MB  (STAGE*NSTAGE)        // full[0..2] at +0,+8,+16 ; empty[0..2] at +24,+32,+40
#define SMEM_TOTAL (STAGE*NSTAGE + 64)

#define NELEM 33554432            // 2*256*256*256
#define ACH 16777216UL            // A-family k-chunk stride (131072 rows * 128B)
#define BCH 32768UL               // B-family k-chunk stride (256 rows * 128B)
#define SLB 262144UL              // per-slice / per-weight B bytes (8 chunks)

// packed hi|lo images: A-family [kc8][m 131072][128B], B-family [s|w][kc8][row 256][128B]
static __device__ __align__(16) __nv_bfloat16 g_P[2*NELEM];
static __device__ __align__(16) __nv_bfloat16 g_A[2*NELEM];
static __device__ __align__(16) __nv_bfloat16 g_H[2*NELEM];
static __device__ __align__(16) __nv_bfloat16 g_B[2*NELEM];
static __device__ __align__(16) __nv_bfloat16 g_W[8*65536];
static __device__ float g_G[NELEM];   // sigmoid gate fp32 natural [m][l]

__device__ __forceinline__ uint32_t pack_bf2(__nv_bfloat16 x, __nv_bfloat16 y) {
    __nv_bfloat162 t = __halves2bfloat162(x, y);
    return *reinterpret_cast<uint32_t*>(&t);
}
__device__ __forceinline__ uint32_t smem_u32(const void* p) {
    uint32_t a;
    asm("{ .reg .u64 t; cvta.to.shared.u64 t, %1; cvt.u32.u64 %0, t; }" : "=r"(a) : "l"(p));
    return a;
}
__device__ __forceinline__ void mma16816(float d[4], const uint32_t a[4], const uint32_t b[2]) {
    asm volatile(
        "mma.sync.aligned.m16n8k16.row.col.f32.bf16.bf16.f32 "
        "{%0,%1,%2,%3}, {%4,%5,%6,%7}, {%8,%9}, {%0,%1,%2,%3};"
        : "+f"(d[0]), "+f"(d[1]), "+f"(d[2]), "+f"(d[3])
        : "r"(a[0]), "r"(a[1]), "r"(a[2]), "r"(a[3]), "r"(b[0]), "r"(b[1]));
}
__device__ __forceinline__ void ldsm_x4(uint32_t r[4], uint32_t a) {
    asm volatile("ldmatrix.sync.aligned.m8n8.x4.shared.b16 {%0,%1,%2,%3}, [%4];"
        : "=r"(r[0]), "=r"(r[1]), "=r"(r[2]), "=r"(r[3]) : "r"(a));
}
__device__ __forceinline__ void split2(float x, float y, uint32_t& H, uint32_t& L) {
    __nv_bfloat16 hx = __float2bfloat16_rn(x), hy = __float2bfloat16_rn(y);
    __nv_bfloat16 lx = __float2bfloat16_rn(x - __bfloat162float(hx));
    __nv_bfloat16 ly = __float2bfloat16_rn(y - __bfloat162float(hy));
    H = pack_bf2(hx, hy); L = pack_bf2(lx, ly);
}

#define MBAR_INIT(a, n) asm volatile("mbarrier.init.shared.b64 [%0], %1;" :: "r"(a), "r"(n) : "memory")
#define MBAR_EXPECT(a, b) asm volatile("mbarrier.arrive.expect_tx.shared.b64 _, [%0], %1;" :: "r"(a), "r"(b) : "memory")
#define MBAR_ARRIVE(a) asm volatile("mbarrier.arrive.shared.b64 _, [%0];" :: "r"(a) : "memory")
#define MBAR_WAIT(a, ph) do { \
    uint32_t _m = (a), _p = (ph), _d; \
    asm volatile("{ .reg .pred p; mbarrier.try_wait.parity.acquire.cta.shared::cta.b64 p, [%1], %2; selp.b32 %0,1,0,p; }" \
        : "=r"(_d) : "r"(_m), "r"(_p) : "memory"); \
    if (!_d) { \
        asm volatile("{ .reg .pred P1; WL_%=: mbarrier.try_wait.parity.acquire.cta.shared::cta.b64 P1, [%0], %1, 0x989680; @P1 bra.uni WD_%=; bra.uni WL_%=; WD_%=: }" \
            :: "r"(_m), "r"(_p) : "memory"); \
    } } while (0)

__device__ __forceinline__ void bulk_cp(uint32_t dst, const char* src, uint32_t bytes, uint32_t mb) {
    asm volatile("cp.async.bulk.shared::cluster.global.mbarrier::complete_tx::bytes [%0], [%1], %2, [%3];"
        :: "r"(dst), "l"(src), "r"(bytes), "r"(mb) : "memory");
}

// swizzled in-row byte position for (row r, byte b in [0,128))
__device__ __forceinline__ uint32_t inrow(int r, int b) {
    return (uint32_t)(((((b >> 4) ^ (r & 7)) << 4)) | (b & 15));
}
__device__ __forceinline__ size_t off_hi(int row, int k, size_t chs) {
    return (size_t)(k >> 5) * chs + (size_t)row * 128 + inrow(row, (k & 31) * 2);
}
__device__ __forceinline__ size_t off_lo(int row, int k, size_t chs) {
    return (size_t)(k >> 5) * chs + (size_t)row * 128 + inrow(row, 64 + (k & 31) * 2);
}
__device__ __forceinline__ void store_split(char* base, int row, int k, float x, float y, size_t chs) {
    uint32_t H, L; split2(x, y, H, L);
    *(uint32_t*)(base + off_hi(row, k, chs)) = H;
    *(uint32_t*)(base + off_lo(row, k, chs)) = L;
}

// issue one K=32 chunk: A tile 16KB + B tile 16KB into stage st
__device__ __forceinline__ void issue_chunk(uint32_t sb, int st,
    const char* Aimg, const char* Bimg, int c)
{
    const uint32_t buf = sb + (uint32_t)st * STAGE;
    const uint32_t mb  = sb + OFF_MB + (uint32_t)st * 8;
    MBAR_EXPECT(mb, 32768u);
    bulk_cp(buf + OFF_A, Aimg + (size_t)c * ACH, 16384, mb);
    bulk_cp(buf + OFF_B, Bimg + (size_t)c * BCH, 16384, mb);
}

// acc[2][8][4]: warp tile 32x64 of C = A[128,256] @ B[128,256]^T-rows.
__device__ __forceinline__ void gemm_compute(uint32_t sb,
    const char* __restrict__ Aimg, const char* __restrict__ Bimg,
    float acc[2][8][4])
{
    const int tid = threadIdx.x;
    const int lane = tid & 31, wid = tid >> 5;
    const int wm = wid >> 1, wn = wid & 1;

#pragma unroll
    for (int mt = 0; mt < 2; ++mt)
#pragma unroll
        for (int nt = 0; nt < 8; ++nt)
#pragma unroll
            for (int i = 0; i < 4; ++i) acc[mt][nt][i] = 0.f;

    if (tid == 0) {
#pragma unroll
        for (int s = 0; s < NSTAGE; ++s) {
            MBAR_INIT(sb + OFF_MB + s * 8, 1);       // full: 1 tx-arrive
            MBAR_INIT(sb + OFF_MB + 24 + s * 8, 8);  // empty: 8 warp arrivals
        }
    }
    __syncthreads();
    if (tid == 0) {
        issue_chunk(sb, 0, Aimg, Bimg, 0);
        issue_chunk(sb, 1, Aimg, Bimg, 1);
    }

    const uint32_t xr     = lane & 7;
    const uint32_t a_base = (uint32_t)(wm*32 + (lane & 15)) * 128;
    const uint32_t a_kh   = lane >> 4;
    const uint32_t b_row  = (lane & 7) + ((lane & 16) >> 1);
    const uint32_t b_base = (uint32_t)(wn*64) * 128 + b_row * 128;
    const uint32_t b_kh   = (lane >> 3) & 1;

#pragma unroll
    for (int c = 0; c < 8; ++c) {
        const int st = c % NSTAGE;
        // producer: issue chunk c+2 (stage last consumed at chunk c-1)
        if (tid == 0 && c + 2 < 8) {
            const int cn = c + 2, st2 = cn % NSTAGE;
            if (cn >= NSTAGE) { MBAR_WAIT(sb + OFF_MB + 24 + st2 * 8, ((cn - NSTAGE) / NSTAGE) & 1); }
            issue_chunk(sb, st2, Aimg, Bimg, cn);
        }
        MBAR_WAIT(sb + OFF_MB + st * 8, (c / NSTAGE) & 1);
        const uint32_t buf = sb + (uint32_t)st * STAGE;
#pragma unroll
        for (int s = 0; s < 2; ++s) {
            const uint32_t ach = (uint32_t)s*2 + a_kh;
            const uint32_t bch = (uint32_t)s*2 + b_kh;
            const uint32_t ax_h = ((ach ^ xr) << 4), ax_l = (((ach + 4) ^ xr) << 4);
            const uint32_t bx_h = ((bch ^ xr) << 4), bx_l = (((bch + 4) ^ xr) << 4);
            uint32_t ah[2][4], al[2][4];
#pragma unroll
            for (int mt = 0; mt < 2; ++mt) {
                const uint32_t ao = buf + OFF_A + a_base + (uint32_t)mt*2048;
                ldsm_x4(ah[mt], ao + ax_h);
                ldsm_x4(al[mt], ao + ax_l);
            }
#pragma unroll
            for (int half = 0; half < 2; ++half) {
                uint32_t bh[2][4], bl[2][4];
#pragma unroll
                for (int p = 0; p < 2; ++p) {
                    const uint32_t bo = buf + OFF_B + b_base + (uint32_t)(half*2 + p)*2048;
                    ldsm_x4(bh[p], bo + bx_h);
                    ldsm_x4(bl[p], bo + bx_l);
                }
#pragma unroll
                for (int mt = 0; mt < 2; ++mt)
#pragma unroll
                    for (int p = 0; p < 2; ++p)
#pragma unroll
                        for (int q = 0; q < 2; ++q)
                            mma16816(acc[mt][half*4 + p*2 + q], ah[mt], &bh[p][q*2]);
#pragma unroll
                for (int mt = 0; mt < 2; ++mt)
#pragma unroll
                    for (int p = 0; p < 2; ++p)
#pragma unroll
                        for (int q = 0; q < 2; ++q)
                            mma16816(acc[mt][half*4 + p*2 + q], ah[mt], &bl[p][q*2]);
#pragma unroll
                for (int mt = 0; mt < 2; ++mt)
#pragma unroll
                    for (int p = 0; p < 2; ++p)
#pragma unroll
                        for (int q = 0; q < 2; ++q)
                            mma16816(acc[mt][half*4 + p*2 + q], al[mt], &bh[p][q*2]);
            }
        }
        // consumption done for this warp: free the stage (arrive after MMAs,
        // whose operand reads guarantee the LDSMs have completed)
        if (lane == 0) MBAR_ARRIVE(sb + OFF_MB + 24 + st * 8);
    }
}

// ---------------- prep kernels ----------------

extern "C" __global__ void psplit_kernel(const float* __restrict__ pair)
{
    const size_t i = ((size_t)blockIdx.x * 256 + threadIdx.x) * 4;
    const int m = (int)(i >> 8), col = (int)(i & 255);
    float4 v = *(const float4*)(pair + i);
    uint32_t H0, L0, H1, L1;
    split2(v.x, v.y, H0, L0);
    split2(v.z, v.w, H1, L1);
    char* base = (char*)g_P;
    *(uint2*)(base + off_hi(m, col, ACH)) = make_uint2(H0, H1);
    *(uint2*)(base + off_lo(m, col, ACH)) = make_uint2(L0, L1);
}

extern "C" __global__ void wprep_kernel(const float* __restrict__ Wa,
                                        const float* __restrict__ Wb,
                                        const float* __restrict__ Wg,
                                        const float* __restrict__ Wo)
{
    const float* Ws[4] = {Wa, Wb, Wg, Wo};
    const int d = blockIdx.x, c = threadIdx.x;
#pragma unroll
    for (int w = 0; w < 4; ++w) {
        float v = Ws[w][c*256 + d];
        __nv_bfloat16 h = __float2bfloat16_rn(v);
        __nv_bfloat16 l = __float2bfloat16_rn(v - __bfloat162float(h));
        char* base = (char*)g_W + (size_t)w * SLB;
        *(__nv_bfloat16*)(base + off_hi(d, c, BCH)) = h;
        *(__nv_bfloat16*)(base + off_lo(d, c, BCH)) = l;
    }
}

// ---------------- GEMM kernels ----------------

// grid (6, 1024): x = w*2 + nt, y = m-tile of 128.
extern "C" __global__ void __launch_bounds__(THREADS, 2)
proj_kernel(const float* __restrict__ ba, const float* __restrict__ bb,
            const float* __restrict__ bg)
{
    extern __shared__ char smem[];
    const uint32_t sb = smem_u32(smem);
    const int w = blockIdx.x >> 1, nt = blockIdx.x & 1;
    const int m0 = blockIdx.y * 128;

    float acc[2][8][4];
    gemm_compute(sb,
                 (const char*)g_P + (size_t)m0*128,
                 (const char*)g_W + (size_t)w*SLB + (size_t)nt*16384,
                 acc);
    __syncthreads();

    const float* bias = (w == 0) ? ba : ((w == 1) ? bb : bg);
    const int wid = threadIdx.x >> 5, lane = threadIdx.x & 31;
    const int wm = wid >> 1, wn = wid & 1;
    const int g = lane >> 2, qc = lane & 3;

    if (w == 1) {
        float* stg = (float*)smem + wid * 2080;  // 32*65
#pragma unroll
        for (int mt = 0; mt < 2; ++mt)
#pragma unroll
            for (int ntl = 0; ntl < 8; ++ntl) {
                const int rm = mt*16 + g, cn = ntl*8 + 2*qc;
                float2 bv = *(const float2*)(bias + nt*128 + wn*64 + cn);
                stg[rm*65 + cn]           = acc[mt][ntl][0] + bv.x;
                stg[rm*65 + cn + 1]       = acc[mt][ntl][1] + bv.y;
                stg[(rm + 8)*65 + cn]     = acc[mt][ntl][2] + bv.x;
                stg[(rm + 8)*65 + cn + 1] = acc[mt][ntl][3] + bv.y;
            }
        __syncwarp();
        const int slice = m0 >> 8;
        const int j0 = (m0 & 255) + wm * 32;
        const int m2 = 2 * (lane & 15);
        const int j = j0 + m2;
        char* base = (char*)g_B + (size_t)slice * SLB;
        for (int r = lane >> 4; r < 64; r += 2) {
            const int l = nt*128 + wn*64 + r;
            store_split(base, l, j, stg[m2*65 + r], stg[(m2 + 1)*65 + r], BCH);
        }
    } else {
#pragma unroll
        for (int mt = 0; mt < 2; ++mt) {
            const int R0 = m0 + wm*32 + mt*16 + g;
#pragma unroll
            for (int ntl = 0; ntl < 8; ++ntl) {
                const int col = nt*128 + wn*64 + ntl*8 + 2*qc;
                float2 bv = *(const float2*)(bias + col);
                float v0 = acc[mt][ntl][0] + bv.x, v1 = acc[mt][ntl][1] + bv.y;
                float v2 = acc[mt][ntl][2] + bv.x, v3 = acc[mt][ntl][3] + bv.y;
                if (w == 2) {
                    v0 = 1.f/(1.f + __expf(-v0)); v1 = 1.f/(1.f + __expf(-v1));
                    v2 = 1.f/(1.f + __expf(-v2)); v3 = 1.f/(1.f + __expf(-v3));
                    *(float2*)(g_G + (size_t)R0*256 + col)       = make_float2(v0, v1);
                    *(float2*)(g_G + (size_t)(R0 + 8)*256 + col) = make_float2(v2, v3);
                } else {
                    store_split((char*)g_A, R0,     col, v0, v1, ACH);
                    store_split((char*)g_A, R0 + 8, col, v2, v3, ACH);
                }
            }
        }
    }
}

// grid (4, 512): x = jt + 2*lt, y = slice. h = g * (a_s @ b_s).
extern "C" __global__ void __launch_bounds__(THREADS, 2)
tri_kernel()
{
    extern __shared__ char smem[];
    const uint32_t sb = smem_u32(smem);
    const int jt = blockIdx.x & 1, lt = blockIdx.x >> 1;
    const int slice = blockIdx.y;

    float acc[2][8][4];
    gemm_compute(sb,
                 (const char*)g_A + (size_t)(slice*256 + jt*128)*128,
                 (const char*)g_B + (size_t)slice*SLB + (size_t)lt*16384,
                 acc);

    const int wid = threadIdx.x >> 5, lane = threadIdx.x & 31;
    const int wm = wid >> 1, wn = wid & 1;
    const int g = lane >> 2, qc = lane & 3;
    const int mbase = slice*256 + jt*128 + wm*32;

#pragma unroll
    for (int mt = 0; mt < 2; ++mt) {
        const int R0 = mbase + mt*16 + g;
#pragma unroll
        for (int ntl = 0; ntl < 8; ++ntl) {
            const int col = lt*128 + wn*64 + ntl*8 + 2*qc;
            float2 g0 = *(const float2*)(g_G + (size_t)R0*256 + col);
            float2 g1 = *(const float2*)(g_G + (size_t)(R0 + 8)*256 + col);
            store_split((char*)g_H, R0,     col, acc[mt][ntl][0]*g0.x, acc[mt][ntl][1]*g0.y, ACH);
            store_split((char*)g_H, R0 + 8, col, acc[mt][ntl][2]*g1.x, acc[mt][ntl][3]*g1.y, ACH);
        }
    }
}

// grid (2, 1024): x = nt, y = m-tile. out = H @ Wo^T-rows + bo.
extern "C" __global__ void __launch_bounds__(THREADS, 2)
out_kernel(const float* __restrict__ bo, float* __restrict__ out)
{
    extern __shared__ char smem[];
    const uint32_t sb = smem_u32(smem);
    const int nt = blockIdx.x;
    const int m0 = blockIdx.y * 128;

    float acc[2][8][4];
    gemm_compute(sb,
                 (const char*)g_H + (size_t)m0*128,
                 (const char*)g_W + (size_t)3*SLB + (size_t)nt*16384,
                 acc);

    const int wid = threadIdx.x >> 5, lane = threadIdx.x & 31;
    const int wm = wid >> 1, wn = wid & 1;
    const int g = lane >> 2, qc = lane & 3;

#pragma unroll
    for (int mt = 0; mt < 2; ++mt) {
        const int R0 = m0 + wm*32 + mt*16 + g;
#pragma unroll
        for (int ntl = 0; ntl < 8; ++ntl) {
            const int col = nt*128 + wn*64 + ntl*8 + 2*qc;
            float2 bv = *(const float2*)(bo + col);
            *(float2*)(out + (size_t)R0*256 + col) =
                make_float2(acc[mt][ntl][0] + bv.x, acc[mt][ntl][1] + bv.y);
            *(float2*)(out + (size_t)(R0 + 8)*256 + col) =
                make_float2(acc[mt][ntl][2] + bv.x, acc[mt][ntl][3] + bv.y);
        }
    }
}

extern "C" void kernel_launch(void* const* d_in, const int* in_sizes, int n_in,
                              void* d_out, int out_size)
{
    const float* pair = (const float*)d_in[0];
    const float* Wa   = (const float*)d_in[1];
    const float* ba   = (const float*)d_in[2];
    const float* Wb   = (const float*)d_in[3];
    const float* bb   = (const float*)d_in[4];
    const float* Wg   = (const float*)d_in[5];
    const float* bg   = (const float*)d_in[6];
    const float* Wo   = (const float*)d_in[7];
    const float* bo   = (const float*)d_in[8];
    float* out = (float*)d_out;

    cudaFuncSetAttribute(proj_kernel, cudaFuncAttributeMaxDynamicSharedMemorySize, SMEM_TOTAL);
    cudaFuncSetAttribute(tri_kernel,  cudaFuncAttributeMaxDynamicSharedMemorySize, SMEM_TOTAL);
    cudaFuncSetAttribute(out_kernel,  cudaFuncAttributeMaxDynamicSharedMemorySize, SMEM_TOTAL);

    wprep_kernel <<<256,   256>>>(Wa, Wb, Wg, Wo);
    psplit_kernel<<<32768, 256>>>(pair);
    proj_kernel<<<dim3(6, 1024), THREADS, SMEM_TOTAL>>>(ba, bb, bg);
    tri_kernel <<<dim3(4, 512),  THREADS, SMEM_TOTAL>>>();
    out_kernel <<<dim3(2, 1024), THREADS, SMEM_TOTAL>>>(bo, out);
}

// round 11
// speedup vs baseline: 3.5642x; 1.3079x over previous
#include <cuda_runtime.h>
#include <cuda_fp16.h>
#include <cstdint>

// TriangleMultiplication, mma.sync m16n8k16 fp16, split-fp16 2-pass fp32 emu:
//   C = Ah*Bh + Al*Bh   (A = fp16 hi+lo, residual 2^-22; B = fp16 hi only,
//   dropped A*Bl term ~2^-11 rel -> ~3e-4 final, under the 1e-3 gate)
// R11: cuts emulation MMAs 3->2 (legacy-HMMA rate is the measured ceiling) and
// halves B smem/DRAM. B rows 64B with XOR key (r>>1)&3 (conflict-free LDSM).

#define THREADS 256
#define OFF_A   0
#define OFF_B   16384
#define STAGE   24576
#define NSTAGE  3
#define OFF_MB  (STAGE*NSTAGE)        // full[0..2] +0,8,16 ; empty[0..2] +24,32,40
#define SMEM_TOTAL (STAGE*NSTAGE + 64)

#define NELEM 33554432            // 2*256*256*256
#define ACH 16777216UL            // A-family k-chunk stride (131072 rows * 128B)
#define BCH 16384UL               // B-family k-chunk stride (256 rows * 64B)
#define SLB 131072UL              // per-slice / per-weight B bytes (8 chunks)

// A-family images [kc8][m 131072][128B: hi 0-63 | lo 64-127], fp16
static __device__ __align__(16) __half g_P[2*NELEM];
static __device__ __align__(16) __half g_A[2*NELEM];
static __device__ __align__(16) __half g_H[2*NELEM];
// B-family images hi-only [.][kc8][row 256][64B], fp16
static __device__ __align__(16) __half g_B[NELEM];
static __device__ __align__(16) __half g_W[4*65536];
static __device__ float g_G[NELEM];   // sigmoid gate fp32 natural [m][l]

__device__ __forceinline__ uint32_t pack_h2(__half x, __half y) {
    __half2 t = __halves2half2(x, y);
    return *reinterpret_cast<uint32_t*>(&t);
}
__device__ __forceinline__ uint32_t smem_u32(const void* p) {
    uint32_t a;
    asm("{ .reg .u64 t; cvta.to.shared.u64 t, %1; cvt.u32.u64 %0, t; }" : "=r"(a) : "l"(p));
    return a;
}
__device__ __forceinline__ void mma16816(float d[4], const uint32_t a[4], const uint32_t b[2]) {
    asm volatile(
        "mma.sync.aligned.m16n8k16.row.col.f32.f16.f16.f32 "
        "{%0,%1,%2,%3}, {%4,%5,%6,%7}, {%8,%9}, {%0,%1,%2,%3};"
        : "+f"(d[0]), "+f"(d[1]), "+f"(d[2]), "+f"(d[3])
        : "r"(a[0]), "r"(a[1]), "r"(a[2]), "r"(a[3]), "r"(b[0]), "r"(b[1]));
}
__device__ __forceinline__ void ldsm_x4(uint32_t r[4], uint32_t a) {
    asm volatile("ldmatrix.sync.aligned.m8n8.x4.shared.b16 {%0,%1,%2,%3}, [%4];"
        : "=r"(r[0]), "=r"(r[1]), "=r"(r[2]), "=r"(r[3]) : "r"(a));
}
__device__ __forceinline__ void split2(float x, float y, uint32_t& H, uint32_t& L) {
    __half hx = __float2half_rn(x), hy = __float2half_rn(y);
    __half lx = __float2half_rn(x - __half2float(hx));
    __half ly = __float2half_rn(y - __half2float(hy));
    H = pack_h2(hx, hy); L = pack_h2(lx, ly);
}

#define MBAR_INIT(a, n) asm volatile("mbarrier.init.shared.b64 [%0], %1;" :: "r"(a), "r"(n) : "memory")
#define MBAR_EXPECT(a, b) asm volatile("mbarrier.arrive.expect_tx.shared.b64 _, [%0], %1;" :: "r"(a), "r"(b) : "memory")
#define MBAR_ARRIVE(a) asm volatile("mbarrier.arrive.shared.b64 _, [%0];" :: "r"(a) : "memory")
#define MBAR_WAIT(a, ph) do { \
    uint32_t _m = (a), _p = (ph), _d; \
    asm volatile("{ .reg .pred p; mbarrier.try_wait.parity.acquire.cta.shared::cta.b64 p, [%1], %2; selp.b32 %0,1,0,p; }" \
        : "=r"(_d) : "r"(_m), "r"(_p) : "memory"); \
    if (!_d) { \
        asm volatile("{ .reg .pred P1; WL_%=: mbarrier.try_wait.parity.acquire.cta.shared::cta.b64 P1, [%0], %1, 0x989680; @P1 bra.uni WD_%=; bra.uni WL_%=; WD_%=: }" \
            :: "r"(_m), "r"(_p) : "memory"); \
    } } while (0)

__device__ __forceinline__ void bulk_cp(uint32_t dst, const char* src, uint32_t bytes, uint32_t mb) {
    asm volatile("cp.async.bulk.shared::cluster.global.mbarrier::complete_tx::bytes [%0], [%1], %2, [%3];"
        :: "r"(dst), "l"(src), "r"(bytes), "r"(mb) : "memory");
}

// A-family: 128B rows, chunk xor key r&7
__device__ __forceinline__ uint32_t inrowA(int r, int b) {
    return (uint32_t)(((((b >> 4) ^ (r & 7)) << 4)) | (b & 15));
}
__device__ __forceinline__ size_t off_hi(int row, int k) {
    return (size_t)(k >> 5) * ACH + (size_t)row * 128 + inrowA(row, (k & 31) * 2);
}
__device__ __forceinline__ size_t off_lo(int row, int k) {
    return (size_t)(k >> 5) * ACH + (size_t)row * 128 + inrowA(row, 64 + (k & 31) * 2);
}
// B-family: 64B rows, chunk xor key (r>>1)&3 (conflict-free over 8-row phases)
__device__ __forceinline__ uint32_t inrowB(int r, int b) {
    return (uint32_t)(((((b >> 4) ^ ((r >> 1) & 3)) << 4)) | (b & 15));
}
__device__ __forceinline__ size_t off_b(int row, int k) {
    return (size_t)(k >> 5) * BCH + (size_t)row * 64 + inrowB(row, (k & 31) * 2);
}
__device__ __forceinline__ void store_splitA(char* base, int row, int k, float x, float y) {
    uint32_t H, L; split2(x, y, H, L);
    *(uint32_t*)(base + off_hi(row, k)) = H;
    *(uint32_t*)(base + off_lo(row, k)) = L;
}

// issue one K=32 chunk: A 16KB (hi+lo) + B 8KB (hi) into stage st
__device__ __forceinline__ void issue_chunk(uint32_t sb, int st,
    const char* Aimg, const char* Bimg, int c)
{
    const uint32_t buf = sb + (uint32_t)st * STAGE;
    const uint32_t mb  = sb + OFF_MB + (uint32_t)st * 8;
    MBAR_EXPECT(mb, 24576u);
    bulk_cp(buf + OFF_A, Aimg + (size_t)c * ACH, 16384, mb);
    bulk_cp(buf + OFF_B, Bimg + (size_t)c * BCH, 8192, mb);
}

// acc[2][8][4]: warp tile 32x64 of C = A[128,256] @ B[128,256]^T-rows.
__device__ __forceinline__ void gemm_compute(uint32_t sb,
    const char* __restrict__ Aimg, const char* __restrict__ Bimg,
    float acc[2][8][4])
{
    const int tid = threadIdx.x;
    const int lane = tid & 31, wid = tid >> 5;
    const int wm = wid >> 1, wn = wid & 1;

#pragma unroll
    for (int mt = 0; mt < 2; ++mt)
#pragma unroll
        for (int nt = 0; nt < 8; ++nt)
#pragma unroll
            for (int i = 0; i < 4; ++i) acc[mt][nt][i] = 0.f;

    if (tid == 0) {
#pragma unroll
        for (int s = 0; s < NSTAGE; ++s) {
            MBAR_INIT(sb + OFF_MB + s * 8, 1);       // full: tx-based
            MBAR_INIT(sb + OFF_MB + 24 + s * 8, 8);  // empty: 8 warp arrivals
        }
    }
    __syncthreads();
    if (tid == 0) {
        issue_chunk(sb, 0, Aimg, Bimg, 0);
        issue_chunk(sb, 1, Aimg, Bimg, 1);
    }

    const uint32_t xr     = lane & 7;
    const uint32_t a_base = (uint32_t)(wm*32 + (lane & 15)) * 128;
    const uint32_t a_kh   = lane >> 4;
    const uint32_t b_row  = (lane & 7) + ((lane & 16) >> 1);
    const uint32_t b_base = ((uint32_t)(wn*64) + b_row) * 64;
    const uint32_t b_kh   = (lane >> 3) & 1;
    const uint32_t bxr    = (lane & 6) >> 1;   // = (row>>1)&3 for this lane's rows

#pragma unroll
    for (int c = 0; c < 8; ++c) {
        const int st = c % NSTAGE;
        if (tid == 0 && c + 2 < 8) {
            const int cn = c + 2, st2 = cn % NSTAGE;
            if (cn >= NSTAGE) { MBAR_WAIT(sb + OFF_MB + 24 + st2 * 8, ((cn - NSTAGE) / NSTAGE) & 1); }
            issue_chunk(sb, st2, Aimg, Bimg, cn);
        }
        MBAR_WAIT(sb + OFF_MB + st * 8, (c / NSTAGE) & 1);
        const uint32_t buf = sb + (uint32_t)st * STAGE;
#pragma unroll
        for (int s = 0; s < 2; ++s) {
            const uint32_t ach = (uint32_t)s*2 + a_kh;                 // A hi chunks 0..3
            const uint32_t ax_h = ((ach ^ xr) << 4), ax_l = (((ach + 4) ^ xr) << 4);
            const uint32_t bx   = (((uint32_t)s*2 + b_kh) ^ bxr) << 4; // B hi chunks 0..3
            uint32_t ah[2][4], al[2][4];
#pragma unroll
            for (int mt = 0; mt < 2; ++mt) {
                const uint32_t ao = buf + OFF_A + a_base + (uint32_t)mt*2048;
                ldsm_x4(ah[mt], ao + ax_h);
                ldsm_x4(al[mt], ao + ax_l);
            }
#pragma unroll
            for (int half = 0; half < 2; ++half) {
                uint32_t bh[2][4];
#pragma unroll
                for (int p = 0; p < 2; ++p) {
                    const uint32_t bo = buf + OFF_B + b_base + (uint32_t)(half*2 + p)*1024;
                    ldsm_x4(bh[p], bo + bx);
                }
                // Pass 1: Ah*Bh
#pragma unroll
                for (int mt = 0; mt < 2; ++mt)
#pragma unroll
                    for (int p = 0; p < 2; ++p)
#pragma unroll
                        for (int q = 0; q < 2; ++q)
                            mma16816(acc[mt][half*4 + p*2 + q], ah[mt], &bh[p][q*2]);
                // Pass 2: Al*Bh
#pragma unroll
                for (int mt = 0; mt < 2; ++mt)
#pragma unroll
                    for (int p = 0; p < 2; ++p)
#pragma unroll
                        for (int q = 0; q < 2; ++q)
                            mma16816(acc[mt][half*4 + p*2 + q], al[mt], &bh[p][q*2]);
            }
        }
        if (lane == 0) MBAR_ARRIVE(sb + OFF_MB + 24 + st * 8);
    }
}

// ---------------- prep kernels ----------------

extern "C" __global__ void psplit_kernel(const float* __restrict__ pair)
{
    const size_t i = ((size_t)blockIdx.x * 256 + threadIdx.x) * 4;
    const int m = (int)(i >> 8), col = (int)(i & 255);
    float4 v = *(const float4*)(pair + i);
    uint32_t H0, L0, H1, L1;
    split2(v.x, v.y, H0, L0);
    split2(v.z, v.w, H1, L1);
    char* base = (char*)g_P;
    *(uint2*)(base + off_hi(m, col)) = make_uint2(H0, H1);
    *(uint2*)(base + off_lo(m, col)) = make_uint2(L0, L1);
}

// weights -> transposed hi-only B images [w][kc8][d 256][64B]
extern "C" __global__ void wprep_kernel(const float* __restrict__ Wa,
                                        const float* __restrict__ Wb,
                                        const float* __restrict__ Wg,
                                        const float* __restrict__ Wo)
{
    const float* Ws[4] = {Wa, Wb, Wg, Wo};
    const int d = blockIdx.x, c = threadIdx.x;
    const size_t off = off_b(d, c);
#pragma unroll
    for (int w = 0; w < 4; ++w) {
        __half h = __float2half_rn(Ws[w][c*256 + d]);
        *(__half*)((char*)g_W + (size_t)w * SLB + off) = h;
    }
}

// ---------------- GEMM kernels ----------------

// grid (6, 1024): x = w*2 + nt, y = m-tile of 128.
extern "C" __global__ void __launch_bounds__(THREADS, 2)
proj_kernel(const float* __restrict__ ba, const float* __restrict__ bb,
            const float* __restrict__ bg)
{
    extern __shared__ char smem[];
    const uint32_t sb = smem_u32(smem);
    const int w = blockIdx.x >> 1, nt = blockIdx.x & 1;
    const int m0 = blockIdx.y * 128;

    float acc[2][8][4];
    gemm_compute(sb,
                 (const char*)g_P + (size_t)m0*128,
                 (const char*)g_W + (size_t)w*SLB + (size_t)nt*8192,
                 acc);
    __syncthreads();

    const float* bias = (w == 0) ? ba : ((w == 1) ? bb : bg);
    const int wid = threadIdx.x >> 5, lane = threadIdx.x & 31;
    const int wm = wid >> 1, wn = wid & 1;
    const int g = lane >> 2, qc = lane & 3;

    if (w == 1) {
        // stage warp tile [32 m][64 n] fp32 -> transposed hi-only store to g_B
        float* stg = (float*)smem + wid * 2080;  // 32*65
#pragma unroll
        for (int mt = 0; mt < 2; ++mt)
#pragma unroll
            for (int ntl = 0; ntl < 8; ++ntl) {
                const int rm = mt*16 + g, cn = ntl*8 + 2*qc;
                float2 bv = *(const float2*)(bias + nt*128 + wn*64 + cn);
                stg[rm*65 + cn]           = acc[mt][ntl][0] + bv.x;
                stg[rm*65 + cn + 1]       = acc[mt][ntl][1] + bv.y;
                stg[(rm + 8)*65 + cn]     = acc[mt][ntl][2] + bv.x;
                stg[(rm + 8)*65 + cn + 1] = acc[mt][ntl][3] + bv.y;
            }
        __syncwarp();
        const int slice = m0 >> 8;
        const int j0 = (m0 & 255) + wm * 32;
        const int m2 = 2 * (lane & 15);
        const int j = j0 + m2;                 // k index (even, j&7 in {0,2,4,6})
        char* base = (char*)g_B + (size_t)slice * SLB;
        for (int r = lane >> 4; r < 64; r += 2) {
            const int l = nt*128 + wn*64 + r;  // row in B image
            uint32_t H = pack_h2(__float2half_rn(stg[m2*65 + r]),
                                 __float2half_rn(stg[(m2 + 1)*65 + r]));
            *(uint32_t*)(base + off_b(l, j)) = H;
        }
    } else {
#pragma unroll
        for (int mt = 0; mt < 2; ++mt) {
            const int R0 = m0 + wm*32 + mt*16 + g;
#pragma unroll
            for (int ntl = 0; ntl < 8; ++ntl) {
                const int col = nt*128 + wn*64 + ntl*8 + 2*qc;
                float2 bv = *(const float2*)(bias + col);
                float v0 = acc[mt][ntl][0] + bv.x, v1 = acc[mt][ntl][1] + bv.y;
                float v2 = acc[mt][ntl][2] + bv.x, v3 = acc[mt][ntl][3] + bv.y;
                if (w == 2) {
                    v0 = 1.f/(1.f + __expf(-v0)); v1 = 1.f/(1.f + __expf(-v1));
                    v2 = 1.f/(1.f + __expf(-v2)); v3 = 1.f/(1.f + __expf(-v3));
                    *(float2*)(g_G + (size_t)R0*256 + col)       = make_float2(v0, v1);
                    *(float2*)(g_G + (size_t)(R0 + 8)*256 + col) = make_float2(v2, v3);
                } else {
                    store_splitA((char*)g_A, R0,     col, v0, v1);
                    store_splitA((char*)g_A, R0 + 8, col, v2, v3);
                }
            }
        }
    }
}

// grid (4, 512): x = jt + 2*lt, y = slice. h = g * (a_s @ b_s).
extern "C" __global__ void __launch_bounds__(THREADS, 2)
tri_kernel()
{
    extern __shared__ char smem[];
    const uint32_t sb = smem_u32(smem);
    const int jt = blockIdx.x & 1, lt = blockIdx.x >> 1;
    const int slice = blockIdx.y;

    float acc[2][8][4];
    gemm_compute(sb,
                 (const char*)g_A + (size_t)(slice*256 + jt*128)*128,
                 (const char*)g_B + (size_t)slice*SLB + (size_t)lt*8192,
                 acc);

    const int wid = threadIdx.x >> 5, lane = threadIdx.x & 31;
    const int wm = wid >> 1, wn = wid & 1;
    const int g = lane >> 2, qc = lane & 3;
    const int mbase = slice*256 + jt*128 + wm*32;

#pragma unroll
    for (int mt = 0; mt < 2; ++mt) {
        const int R0 = mbase + mt*16 + g;
#pragma unroll
        for (int ntl = 0; ntl < 8; ++ntl) {
            const int col = lt*128 + wn*64 + ntl*8 + 2*qc;
            float2 g0 = *(const float2*)(g_G + (size_t)R0*256 + col);
            float2 g1 = *(const float2*)(g_G + (size_t)(R0 + 8)*256 + col);
            store_splitA((char*)g_H, R0,     col, acc[mt][ntl][0]*g0.x, acc[mt][ntl][1]*g0.y);
            store_splitA((char*)g_H, R0 + 8, col, acc[mt][ntl][2]*g1.x, acc[mt][ntl][3]*g1.y);
        }
    }
}

// grid (2, 1024): x = nt, y = m-tile. out = H @ Wo^T-rows + bo.
extern "C" __global__ void __launch_bounds__(THREADS, 2)
out_kernel(const float* __restrict__ bo, float* __restrict__ out)
{
    extern __shared__ char smem[];
    const uint32_t sb = smem_u32(smem);
    const int nt = blockIdx.x;
    const int m0 = blockIdx.y * 128;

    float acc[2][8][4];
    gemm_compute(sb,
                 (const char*)g_H + (size_t)m0*128,
                 (const char*)g_W + (size_t)3*SLB + (size_t)nt*8192,
                 acc);

    const int wid = threadIdx.x >> 5, lane = threadIdx.x & 31;
    const int wm = wid >> 1, wn = wid & 1;
    const int g = lane >> 2, qc = lane & 3;

#pragma unroll
    for (int mt = 0; mt < 2; ++mt) {
        const int R0 = m0 + wm*32 + mt*16 + g;
#pragma unroll
        for (int ntl = 0; ntl < 8; ++ntl) {
            const int col = nt*128 + wn*64 + ntl*8 + 2*qc;
            float2 bv = *(const float2*)(bo + col);
            *(float2*)(out + (size_t)R0*256 + col) =
                make_float2(acc[mt][ntl][0] + bv.x, acc[mt][ntl][1] + bv.y);
            *(float2*)(out + (size_t)(R0 + 8)*256 + col) =
                make_float2(acc[mt][ntl][2] + bv.x, acc[mt][ntl][3] + bv.y);
        }
    }
}

extern "C" void kernel_launch(void* const* d_in, const int* in_sizes, int n_in,
                              void* d_out, int out_size)
{
    const float* pair = (const float*)d_in[0];
    const float* Wa   = (const float*)d_in[1];
    const float* ba   = (const float*)d_in[2];
    const float* Wb   = (const float*)d_in[3];
    const float* bb   = (const float*)d_in[4];
    const float* Wg   = (const float*)d_in[5];
    const float* bg   = (const float*)d_in[6];
    const float* Wo   = (const float*)d_in[7];
    const float* bo   = (const float*)d_in[8];
    float* out = (float*)d_out;

    cudaFuncSetAttribute(proj_kernel, cudaFuncAttributeMaxDynamicSharedMemorySize, SMEM_TOTAL);
    cudaFuncSetAttribute(tri_kernel,  cudaFuncAttributeMaxDynamicSharedMemorySize, SMEM_TOTAL);
    cudaFuncSetAttribute(out_kernel,  cudaFuncAttributeMaxDynamicSharedMemorySize, SMEM_TOTAL);

    wprep_kernel <<<256,   256>>>(Wa, Wb, Wg, Wo);
    psplit_kernel<<<32768, 256>>>(pair);
    proj_kernel<<<dim3(6, 1024), THREADS, SMEM_TOTAL>>>(ba, bb, bg);
    tri_kernel <<<dim3(4, 512),  THREADS, SMEM_TOTAL>>>();
    out_kernel <<<dim3(2, 1024), THREADS, SMEM_TOTAL>>>(bo, out);
}